// round 9
// baseline (speedup 1.0000x reference)
#include <cuda_runtime.h>
#include <cuda_fp16.h>

#define ALPHA 0.2f
#define BN_EPS 1e-5f
#define THREADS 768
#define WARPS 24

typedef unsigned int u32;
typedef unsigned long long u64;

__device__ __forceinline__ u32 pkh(float a, float b){
    __half2 h = __floats2half2_rn(a, b);
    return *(u32*)&h;
}
__device__ __forceinline__ u64 ffma2(u64 a, u64 b, u64 c){
    u64 d; asm("fma.rn.f32x2 %0, %1, %2, %3;" : "=l"(d) : "l"(a), "l"(b), "l"(c)); return d;
}
__device__ __forceinline__ u64 pk(float lo, float hi){
    u64 r; asm("mov.b64 %0, {%1, %2};" : "=l"(r) : "f"(lo), "f"(hi)); return r;
}
__device__ __forceinline__ float hsum(u64 v){
    float x, y; asm("mov.b64 {%0, %1}, %2;" : "=f"(x), "=f"(y) : "l"(v)); return x + y;
}
__device__ __forceinline__ float wsum(float v){
    #pragma unroll
    for (int d = 16; d > 0; d >>= 1) v += __shfl_xor_sync(0xffffffffu, v, d);
    return v;
}
// m16n8k16 fp16 MMA, fp32 accum
__device__ __forceinline__ void mma16(float4& d, u32 a0, u32 a1, u32 a2, u32 a3, u32 b0, u32 b1){
    asm("mma.sync.aligned.m16n8k16.row.col.f32.f16.f16.f32 "
        "{%0,%1,%2,%3}, {%4,%5,%6,%7}, {%8,%9}, {%0,%1,%2,%3};"
        : "+f"(d.x), "+f"(d.y), "+f"(d.z), "+f"(d.w)
        : "r"(a0), "r"(a1), "r"(a2), "r"(a3), "r"(b0), "r"(b1));
}

// ---- shared memory layout (32-bit slots) ----
#define BF1_OFF   0        // [8 q][9 t][32 lane] uint2 fp16 B frags L1 (t=8: score cols) = 4608
#define BF2_OFF   4608     // [4 q][5 t][32] uint2 (t=4: score cols) = 1280 -> 5888
#define WL2_OFF   5888     // [13 k][5 n][32 lane] float2 = 4160 -> 10048
#define SC1_OFF   10048
#define SH1_OFF   10056
#define SC2_OFF   10064
#define SH2_OFF   10072
#define BL_OFF    10080    // 13 (pad 16) -> 10096
#define SCR_OFF   10096
// per-warp scratch (1568 slots):
//   phase 1: xh[2][10 rows][68 u32] fp16x2 x rows = 1360
//   overlays in [0,1360): H f32 (stride 68, 680/batch) -> h2 fp16x2 (stride 36)
//                         -> hh f32 (stride 34)
//   SB1 [1360,1400)  SB2 [1400,1440)  AB [1440,1568): attn 2 x 64
// init-time temp (block scope, overlays warp scratch): w1a[0,125), w2a[128,253),
//   w1a2[256,320), w2a2[320,384)
#define WSCR      1568
#define SMEM_FLOATS (SCR_OFF + WARPS*WSCR)   // 47728 slots = 190912 bytes

__global__ void __launch_bounds__(THREADS, 1) gat_fused_kernel(
    const float* __restrict__ x,
    const float* __restrict__ Wt1, const float* __restrict__ a11, const float* __restrict__ a21,
    const float* __restrict__ g1,  const float* __restrict__ b1,  const float* __restrict__ m1, const float* __restrict__ v1,
    const float* __restrict__ Wt2, const float* __restrict__ a12, const float* __restrict__ a22,
    const float* __restrict__ g2,  const float* __restrict__ b2,  const float* __restrict__ m2, const float* __restrict__ v2,
    const float* __restrict__ Wl,  const float* __restrict__ bl,
    float* __restrict__ out, int B)
{
    extern __shared__ float sm[];
    const int tid = threadIdx.x;

    // -------- init phase A: folded score vectors w = W^T a (fp32, to temp smem) ----
    {
        float* wtmp = sm + SCR_OFF;
        for (int i = tid; i < 250; i += THREADS){
            int v = (i >= 125), k = i - v*125;
            const float* av = v ? a21 : a11;
            float s = 0.f;
            #pragma unroll 8
            for (int n = 0; n < 64; n++) s += av[n] * Wt1[n*125 + k];
            wtmp[v*128 + k] = s;
        }
        for (int i = tid; i < 128; i += THREADS){
            int v = (i >= 64), k = i & 63;
            const float* av = v ? a22 : a12;
            float s = 0.f;
            #pragma unroll 8
            for (int n = 0; n < 32; n++) s += av[n] * Wt2[n*64 + k];
            wtmp[256 + v*64 + k] = s;
        }
    }
    __syncthreads();

    // -------- init phase B: stage fp16 B-fragments (incl. score tiles) -------------
    {
        const float* w1a  = sm + SCR_OFF;
        const float* w2a  = sm + SCR_OFF + 128;
        const float* w1a2 = sm + SCR_OFF + 256;
        const float* w2a2 = sm + SCR_OFF + 320;

        uint2* bf1 = (uint2*)(sm + BF1_OFF);
        for (int i = tid; i < 8*9*32; i += THREADS){
            int l = i & 31, tt = i >> 5;
            int t = tt % 9, q = tt / 9;
            int k0 = 16*q + 2*(l & 3);
            uint2 val;
            if (t < 8){
                int n = 8*t + (l >> 2);
                float w0 = (k0   < 125) ? Wt1[n*125 + k0    ] : 0.f;
                float w1 = (k0+1 < 125) ? Wt1[n*125 + k0 + 1] : 0.f;
                float w8 = (k0+8 < 125) ? Wt1[n*125 + k0 + 8] : 0.f;
                float w9 = (k0+9 < 125) ? Wt1[n*125 + k0 + 9] : 0.f;
                val = make_uint2(pkh(w0, w1), pkh(w8, w9));
            } else {
                int c = l >> 2;   // col 64+c: c==0 -> w1a, c==1 -> w2a, else 0
                const float* wv = (c == 0) ? w1a : w2a;
                if (c < 2){
                    float w0 = (k0   < 125) ? wv[k0    ] : 0.f;
                    float w1 = (k0+1 < 125) ? wv[k0 + 1] : 0.f;
                    float w8 = (k0+8 < 125) ? wv[k0 + 8] : 0.f;
                    float w9 = (k0+9 < 125) ? wv[k0 + 9] : 0.f;
                    val = make_uint2(pkh(w0, w1), pkh(w8, w9));
                } else val = make_uint2(0u, 0u);
            }
            bf1[(q*9 + t)*32 + l] = val;
        }
        uint2* bf2 = (uint2*)(sm + BF2_OFF);
        for (int i = tid; i < 4*5*32; i += THREADS){
            int l = i & 31, tt = i >> 5;
            int t = tt % 5, q = tt / 5;
            int k0 = 16*q + 2*(l & 3);
            uint2 val;
            if (t < 4){
                int n = 8*t + (l >> 2);
                val = make_uint2(pkh(Wt2[n*64 + k0    ], Wt2[n*64 + k0 + 1]),
                                 pkh(Wt2[n*64 + k0 + 8], Wt2[n*64 + k0 + 9]));
            } else {
                int c = l >> 2;
                const float* wv = (c == 0) ? w1a2 : w2a2;
                if (c < 2)
                    val = make_uint2(pkh(wv[k0], wv[k0+1]), pkh(wv[k0+8], wv[k0+9]));
                else val = make_uint2(0u, 0u);
            }
            bf2[(q*5 + t)*32 + l] = val;
        }
        float2* wlp = (float2*)(sm + WL2_OFF);       // [k][n][lane]
        for (int i = tid; i < 13*5*32; i += THREADS){
            int k = i / 160, r = i - k*160;
            int n = r >> 5, l = r & 31;
            wlp[i] = make_float2(Wl[k*320 + n*64 + l], Wl[k*320 + n*64 + 32 + l]);
        }
        if (tid < 5){
            float sc = g1[tid] * rsqrtf(v1[tid] + BN_EPS);
            sm[SC1_OFF+tid] = sc; sm[SH1_OFF+tid] = b1[tid] - m1[tid]*sc;
            float s2c = g2[tid] * rsqrtf(v2[tid] + BN_EPS);
            sm[SC2_OFF+tid] = s2c; sm[SH2_OFF+tid] = b2[tid] - m2[tid]*s2c;
        }
        if (tid < 13) sm[BL_OFF+tid] = bl[tid];
    }
    __syncthreads();

    const int wid  = tid >> 5, lane = tid & 31;
    const int gid  = lane >> 2, tig = lane & 3;   // fragment coords
    const int hi_ok = (gid < 2);
    const int b0i = (blockIdx.x * WARPS + wid) * 2;
    if (b0i >= B) return;
    const int has_b1 = (b0i + 1 < B);
    const int b1i = has_b1 ? (b0i + 1) : b0i;

    float* ws = sm + SCR_OFF + wid*WSCR;
    u32*   xh = (u32*)ws;                    // fp16x2 x rows, stride 68 u32

    // ---------------- load x (2 batches) -> fp16 A rows ----------------
    {
        const int L2 = 2*lane;
        #pragma unroll
        for (int bi = 0; bi < 2; bi++){
            const float* xg = x + (size_t)(bi ? b1i : b0i) * 1250;
            u32* xsb = xh + bi*680;
            #pragma unroll
            for (int inp = 0; inp < 2; inp++)
                #pragma unroll
                for (int n = 0; n < 5; n++){
                    const float* src = xg + n*250 + inp*125;
                    u32* dst = xsb + (inp*5 + n)*68;
                    dst[lane] = pkh(src[L2], src[L2+1]);
                    float c0 = (L2+64 < 125) ? src[L2+64] : 0.f;
                    float c1 = (L2+65 < 125) ? src[L2+65] : 0.f;
                    dst[lane+32] = pkh(c0, c1);
                }
        }
    }
    __syncwarp();

    // ------- layer 1 MMA: 9 N-tiles (8 data + 1 score), K=128 in 8 k16-steps -----
    float4 d1[2][9];
    #pragma unroll
    for (int bi = 0; bi < 2; bi++)
        #pragma unroll
        for (int t = 0; t < 9; t++) d1[bi][t] = make_float4(0.f, 0.f, 0.f, 0.f);
    {
        const int hi_row = hi_ok ? (gid+8)*68 : 0;
        const u32* xa0lo = xh + gid*68 + tig;
        const u32* xa0hi = xh + hi_row + tig;
        const u32* xa1lo = xa0lo + 680;
        const u32* xa1hi = xa0hi + 680;
        const uint2* bf1 = (const uint2*)(sm + BF1_OFF);
        #pragma unroll
        for (int q = 0; q < 8; q++){
            u32 a00 = xa0lo[8*q], a01 = xa0hi[8*q];
            u32 a02 = xa0lo[8*q + 4], a03 = xa0hi[8*q + 4];
            u32 a10 = xa1lo[8*q], a11r = xa1hi[8*q];
            u32 a12r = xa1lo[8*q + 4], a13 = xa1hi[8*q + 4];
            #pragma unroll
            for (int t = 0; t < 9; t++){
                uint2 bb = bf1[(q*9 + t)*32 + lane];
                mma16(d1[0][t], a00, a01, a02, a03, bb.x, bb.y);
                mma16(d1[1][t], a10, a11r, a12r, a13, bb.x, bb.y);
            }
        }
    }
    __syncwarp();   // all xh reads done before H overlay writes

    // ---- layer 1: scores direct from tile 8; spill H rows (f32, stride 68) ------
    #pragma unroll
    for (int bi = 0; bi < 2; bi++){
        float2* sb = (float2*)(ws + 1360) + bi*10;
        if (tig == 0){
            sb[gid] = make_float2(d1[bi][8].x, d1[bi][8].y);
            if (hi_ok) sb[8 + gid] = make_float2(d1[bi][8].z, d1[bi][8].w);
        }
        float* hb = ws + bi*680;   // f32, stride 68
        #pragma unroll
        for (int t = 0; t < 8; t++){
            int col = 8*t + 2*tig;
            *(float2*)(hb + gid*68 + col) = make_float2(d1[bi][t].x, d1[bi][t].y);
            if (hi_ok)
                *(float2*)(hb + (gid+8)*68 + col) = make_float2(d1[bi][t].z, d1[bi][t].w);
        }
    }
    __syncwarp();

    // ---------------- merged layer 1 softmax (20 lanes, both batches) -----------
    {
        int bb_ = lane / 10, r = lane - 10*bb_;
        int g = r / 5, j = r - 5*g;
        if (lane < 20){
            const float2* sb = (const float2*)(ws + 1360) + bb_*10;
            float* abuf = ws + 1440 + bb_*64;
            float t2j = sb[g*5 + j].y;
            float ex[5], cs = 0.f;
            #pragma unroll
            for (int i = 0; i < 5; i++){
                float e = sb[g*5 + i].x + t2j;
                e = (e > 0.f) ? e : ALPHA*e;
                ex[i] = __expf(e);
                cs += ex[i];
            }
            float rc = __fdividef(1.f, cs);
            #pragma unroll
            for (int i = 0; i < 5; i++) abuf[g*32 + i*5 + j] = ex[i]*rc;
        }
    }
    __syncwarp();

    // ---------------- apply1 + BN1 + ReLU -> h2 fp16 (stride 36) ----------------
    #pragma unroll
    for (int bi = 0; bi < 2; bi++){
        const float* hb = ws + bi*680;
        const float* abuf = ws + 1440 + bi*64;
        float Ox[2][5], Oy[2][5];
        #pragma unroll
        for (int inp = 0; inp < 2; inp++)
            #pragma unroll
            for (int i = 0; i < 5; i++){ Ox[inp][i] = 0.f; Oy[inp][i] = 0.f; }
        #pragma unroll
        for (int inp = 0; inp < 2; inp++)
            #pragma unroll
            for (int j = 0; j < 5; j++){
                float2 Hp = *(const float2*)(hb + (inp*5 + j)*68 + 2*lane);
                #pragma unroll
                for (int i = 0; i < 5; i++){
                    float a = abuf[inp*32 + i*5 + j];
                    Ox[inp][i] += a * Hp.x;
                    Oy[inp][i] += a * Hp.y;
                }
            }
        __syncwarp();   // H reads complete before fp16 overlay
        u32* h2 = (u32*)(ws + bi*680);   // fp16x2, stride 36 u32
        #pragma unroll
        for (int inp = 0; inp < 2; inp++)
            #pragma unroll
            for (int n = 0; n < 5; n++){
                float sc = sm[SC1_OFF+n], sh = sm[SH1_OFF+n];
                float v0 = fmaxf(0.f, Ox[inp][n]*sc + sh);
                float v1 = fmaxf(0.f, Oy[inp][n]*sc + sh);
                h2[(inp*5 + n)*36 + lane] = pkh(v0, v1);
            }
        __syncwarp();
    }

    // ------- layer 2 MMA: 5 N-tiles (4 data + 1 score), K=64 in 4 k16-steps ------
    float4 d2[2][5];
    #pragma unroll
    for (int bi = 0; bi < 2; bi++)
        #pragma unroll
        for (int t = 0; t < 5; t++) d2[bi][t] = make_float4(0.f, 0.f, 0.f, 0.f);
    {
        const int hi_row2 = hi_ok ? (gid+8)*36 : 0;
        const u32* ha0lo = (const u32*)ws + gid*36 + tig;
        const u32* ha0hi = (const u32*)ws + hi_row2 + tig;
        const u32* ha1lo = ha0lo + 680;
        const u32* ha1hi = ha0hi + 680;
        const uint2* bf2 = (const uint2*)(sm + BF2_OFF);
        #pragma unroll
        for (int q = 0; q < 4; q++){
            u32 a00 = ha0lo[8*q], a01 = ha0hi[8*q];
            u32 a02 = ha0lo[8*q + 4], a03 = ha0hi[8*q + 4];
            u32 a10 = ha1lo[8*q], a11r = ha1hi[8*q];
            u32 a12r = ha1lo[8*q + 4], a13 = ha1hi[8*q + 4];
            #pragma unroll
            for (int t = 0; t < 5; t++){
                uint2 bb = bf2[(q*5 + t)*32 + lane];
                mma16(d2[0][t], a00, a01, a02, a03, bb.x, bb.y);
                mma16(d2[1][t], a10, a11r, a12r, a13, bb.x, bb.y);
            }
        }
    }
    __syncwarp();   // h2 reads done before hh overlay

    // ---- layer 2: scores direct from tile 4; spill hh rows (f32, stride 34) -----
    #pragma unroll
    for (int bi = 0; bi < 2; bi++){
        float2* sb2 = (float2*)(ws + 1400) + bi*10;
        if (tig == 0){
            sb2[gid] = make_float2(d2[bi][4].x, d2[bi][4].y);
            if (hi_ok) sb2[8 + gid] = make_float2(d2[bi][4].z, d2[bi][4].w);
        }
        float* hhb = ws + bi*680;   // f32, stride 34
        #pragma unroll
        for (int t = 0; t < 4; t++){
            int col = 8*t + 2*tig;
            *(float2*)(hhb + gid*34 + col) = make_float2(d2[bi][t].x, d2[bi][t].y);
            if (hi_ok)
                *(float2*)(hhb + (gid+8)*34 + col) = make_float2(d2[bi][t].z, d2[bi][t].w);
        }
    }
    __syncwarp();

    // ---------------- merged layer 2 softmax (20 lanes) -------------------------
    {
        int bb_ = lane / 10, r = lane - 10*bb_;
        int g = r / 5, j = r - 5*g;
        if (lane < 20){
            const float2* sb2 = (const float2*)(ws + 1400) + bb_*10;
            float* abuf = ws + 1440 + bb_*64;
            float t2j = sb2[(1-g)*5 + j].y;
            float ex[5], cs = 0.f;
            #pragma unroll
            for (int i = 0; i < 5; i++){
                float e = sb2[g*5 + i].x + t2j;
                e = (e > 0.f) ? e : ALPHA*e;
                ex[i] = __expf(e);
                cs += ex[i];
            }
            float rc = __fdividef(1.f, cs);
            #pragma unroll
            for (int i = 0; i < 5; i++) abuf[g*32 + i*5 + j] = ex[i]*rc;
        }
    }
    __syncwarp();

    // ---------------- apply2 + BN2 + ReLU ----------------
    float y2[2][2][5];
    #pragma unroll
    for (int bi = 0; bi < 2; bi++){
        const float* hhb = ws + bi*680;
        const float* abuf = ws + 1440 + bi*64;
        float hv[2][5];
        #pragma unroll
        for (int g = 0; g < 2; g++)
            #pragma unroll
            for (int j = 0; j < 5; j++)
                hv[g][j] = hhb[(g*5 + j)*34 + lane];
        #pragma unroll
        for (int g = 0; g < 2; g++)
            #pragma unroll
            for (int i = 0; i < 5; i++){
                float o2 = 0.f;
                #pragma unroll
                for (int j = 0; j < 5; j++)
                    o2 += abuf[g*32 + i*5 + j] * hv[g][j];
                y2[bi][g][i] = fmaxf(0.f, o2*sm[SC2_OFF+i] + sm[SH2_OFF+i]);
            }
    }

    // ---------------- final linear (shared Wl loads, both batches) --------------
    u64 f2a[5], f2b[5];
    #pragma unroll
    for (int n = 0; n < 5; n++){
        f2a[n] = pk(y2[0][0][n], y2[0][1][n]);
        f2b[n] = pk(y2[1][0][n], y2[1][1][n]);
    }
    const u64* wlp = (const u64*)(sm + WL2_OFF);
    float res0 = 0.f, res1 = 0.f;
    #pragma unroll
    for (int k = 0; k < 13; k++){
        u64 aa = 0ull, ab = 0ull;
        #pragma unroll
        for (int n = 0; n < 5; n++){
            u64 w = wlp[k*160 + n*32 + lane];
            aa = ffma2(f2a[n], w, aa);
            ab = ffma2(f2b[n], w, ab);
        }
        float r0 = wsum(hsum(aa));
        float r1 = wsum(hsum(ab));
        if (lane == k){ res0 = r0 + sm[BL_OFF+k]; res1 = r1 + sm[BL_OFF+k]; }
    }
    if (lane < 13){
        out[(size_t)b0i*13 + lane] = res0;
        if (has_b1) out[(size_t)b1i*13 + lane] = res1;
    }
}

extern "C" void kernel_launch(void* const* d_in, const int* in_sizes, int n_in,
                              void* d_out, int out_size)
{
    const float* x   = (const float*)d_in[0];
    const float* Wt1 = (const float*)d_in[1];
    const float* a11 = (const float*)d_in[2];
    const float* a21 = (const float*)d_in[3];
    const float* g1  = (const float*)d_in[4];
    const float* b1  = (const float*)d_in[5];
    const float* m1  = (const float*)d_in[6];
    const float* v1  = (const float*)d_in[7];
    const float* Wt2 = (const float*)d_in[8];
    const float* a12 = (const float*)d_in[9];
    const float* a22 = (const float*)d_in[10];
    const float* g2  = (const float*)d_in[11];
    const float* b2  = (const float*)d_in[12];
    const float* m2  = (const float*)d_in[13];
    const float* v2  = (const float*)d_in[14];
    const float* Wl  = (const float*)d_in[15];
    const float* bl  = (const float*)d_in[16];

    int B = in_sizes[0] / 1250;
    size_t smem_bytes = (size_t)SMEM_FLOATS * sizeof(float);
    cudaFuncSetAttribute(gat_fused_kernel,
                         cudaFuncAttributeMaxDynamicSharedMemorySize, (int)smem_bytes);

    int batches_per_block = WARPS * 2;
    dim3 grid((B + batches_per_block - 1) / batches_per_block);
    gat_fused_kernel<<<grid, THREADS, smem_bytes>>>(
        x, Wt1, a11, a21, g1, b1, m1, v1,
        Wt2, a12, a22, g2, b2, m2, v2, Wl, bl,
        (float*)d_out, B);
}

// round 10
// speedup vs baseline: 1.4843x; 1.4843x over previous
#include <cuda_runtime.h>
#include <cuda_fp16.h>

#define ALPHA 0.2f
#define BN_EPS 1e-5f
#define THREADS 640
#define WARPS 20
#define NBLOCKS 148

typedef unsigned int u32;
typedef unsigned long long u64;

__device__ __forceinline__ u32 pkh(float a, float b){
    __half2 h = __floats2half2_rn(a, b);
    return *(u32*)&h;
}
__device__ __forceinline__ u64 ffma2(u64 a, u64 b, u64 c){
    u64 d; asm("fma.rn.f32x2 %0, %1, %2, %3;" : "=l"(d) : "l"(a), "l"(b), "l"(c)); return d;
}
__device__ __forceinline__ u64 pk(float lo, float hi){
    u64 r; asm("mov.b64 %0, {%1, %2};" : "=l"(r) : "f"(lo), "f"(hi)); return r;
}
__device__ __forceinline__ float hsum(u64 v){
    float x, y; asm("mov.b64 {%0, %1}, %2;" : "=f"(x), "=f"(y) : "l"(v)); return x + y;
}
__device__ __forceinline__ float wsum(float v){
    #pragma unroll
    for (int d = 16; d > 0; d >>= 1) v += __shfl_xor_sync(0xffffffffu, v, d);
    return v;
}
// m16n8k16 fp16 MMA, fp32 accum
__device__ __forceinline__ void mma16(float4& d, u32 a0, u32 a1, u32 a2, u32 a3, u32 b0, u32 b1){
    asm("mma.sync.aligned.m16n8k16.row.col.f32.f16.f16.f32 "
        "{%0,%1,%2,%3}, {%4,%5,%6,%7}, {%8,%9}, {%0,%1,%2,%3};"
        : "+f"(d.x), "+f"(d.y), "+f"(d.z), "+f"(d.w)
        : "r"(a0), "r"(a1), "r"(a2), "r"(a3), "r"(b0), "r"(b1));
}

// ---- shared memory layout (32-bit slots) ----
#define BF1_OFF   0        // [8 q][9 t][32 lane] uint2 fp16 B frags L1 (t=8: score cols) = 4608
#define BF2_OFF   4608     // [4 q][5 t][32] uint2 (t=4: score cols) = 1280 -> 5888
#define WL2_OFF   5888     // [13 k][5 n][32 lane] float2 = 4160 -> 10048
#define SC1_OFF   10048
#define SH1_OFF   10056
#define SC2_OFF   10064
#define SH2_OFF   10072
#define BL_OFF    10080    // 13 (pad 16) -> 10096
#define SCR_OFF   10096
// per-warp scratch (1568 slots):
//   phase 1: xh[2][10 rows][68 u32] fp16x2 x rows = 1360
//   overlays in [0,1360): H f32 (stride 68, 680/batch) -> h2 fp16x2 (stride 36)
//                         -> hh f32 (stride 34)
//   SB1 [1360,1400)  SB2 [1400,1440)  AB [1440,1568): attn 2 x 64
// init-time temp (block scope, overlays warp scratch): w1a[0,125), w2a[128,253),
//   w1a2[256,320), w2a2[320,384)
#define WSCR      1568
#define SMEM_FLOATS (SCR_OFF + WARPS*WSCR)   // 41456 slots = 165824 bytes

__global__ void __launch_bounds__(THREADS, 1) gat_fused_kernel(
    const float* __restrict__ x,
    const float* __restrict__ Wt1, const float* __restrict__ a11, const float* __restrict__ a21,
    const float* __restrict__ g1,  const float* __restrict__ b1,  const float* __restrict__ m1, const float* __restrict__ v1,
    const float* __restrict__ Wt2, const float* __restrict__ a12, const float* __restrict__ a22,
    const float* __restrict__ g2,  const float* __restrict__ b2,  const float* __restrict__ m2, const float* __restrict__ v2,
    const float* __restrict__ Wl,  const float* __restrict__ bl,
    float* __restrict__ out, int B)
{
    extern __shared__ float sm[];
    const int tid = threadIdx.x;

    // -------- init phase A: folded score vectors w = W^T a (fp32, to temp smem) ----
    {
        float* wtmp = sm + SCR_OFF;
        for (int i = tid; i < 250; i += THREADS){
            int v = (i >= 125), k = i - v*125;
            const float* av = v ? a21 : a11;
            float s = 0.f;
            #pragma unroll 8
            for (int n = 0; n < 64; n++) s += av[n] * Wt1[n*125 + k];
            wtmp[v*128 + k] = s;
        }
        for (int i = tid; i < 128; i += THREADS){
            int v = (i >= 64), k = i & 63;
            const float* av = v ? a22 : a12;
            float s = 0.f;
            #pragma unroll 8
            for (int n = 0; n < 32; n++) s += av[n] * Wt2[n*64 + k];
            wtmp[256 + v*64 + k] = s;
        }
    }
    __syncthreads();

    // -------- init phase B: stage fp16 B-fragments (incl. score tiles) -------------
    {
        const float* w1a  = sm + SCR_OFF;
        const float* w2a  = sm + SCR_OFF + 128;
        const float* w1a2 = sm + SCR_OFF + 256;
        const float* w2a2 = sm + SCR_OFF + 320;

        uint2* bf1 = (uint2*)(sm + BF1_OFF);
        for (int i = tid; i < 8*9*32; i += THREADS){
            int l = i & 31, tt = i >> 5;
            int t = tt % 9, q = tt / 9;
            int k0 = 16*q + 2*(l & 3);
            uint2 val;
            if (t < 8){
                int n = 8*t + (l >> 2);
                float w0 = (k0   < 125) ? Wt1[n*125 + k0    ] : 0.f;
                float w1 = (k0+1 < 125) ? Wt1[n*125 + k0 + 1] : 0.f;
                float w8 = (k0+8 < 125) ? Wt1[n*125 + k0 + 8] : 0.f;
                float w9 = (k0+9 < 125) ? Wt1[n*125 + k0 + 9] : 0.f;
                val = make_uint2(pkh(w0, w1), pkh(w8, w9));
            } else {
                int c = l >> 2;   // col 64+c: c==0 -> w1a, c==1 -> w2a, else 0
                const float* wv = (c == 0) ? w1a : w2a;
                if (c < 2){
                    float w0 = (k0   < 125) ? wv[k0    ] : 0.f;
                    float w1 = (k0+1 < 125) ? wv[k0 + 1] : 0.f;
                    float w8 = (k0+8 < 125) ? wv[k0 + 8] : 0.f;
                    float w9 = (k0+9 < 125) ? wv[k0 + 9] : 0.f;
                    val = make_uint2(pkh(w0, w1), pkh(w8, w9));
                } else val = make_uint2(0u, 0u);
            }
            bf1[(q*9 + t)*32 + l] = val;
        }
        uint2* bf2 = (uint2*)(sm + BF2_OFF);
        for (int i = tid; i < 4*5*32; i += THREADS){
            int l = i & 31, tt = i >> 5;
            int t = tt % 5, q = tt / 5;
            int k0 = 16*q + 2*(l & 3);
            uint2 val;
            if (t < 4){
                int n = 8*t + (l >> 2);
                val = make_uint2(pkh(Wt2[n*64 + k0    ], Wt2[n*64 + k0 + 1]),
                                 pkh(Wt2[n*64 + k0 + 8], Wt2[n*64 + k0 + 9]));
            } else {
                int c = l >> 2;
                const float* wv = (c == 0) ? w1a2 : w2a2;
                if (c < 2)
                    val = make_uint2(pkh(wv[k0], wv[k0+1]), pkh(wv[k0+8], wv[k0+9]));
                else val = make_uint2(0u, 0u);
            }
            bf2[(q*5 + t)*32 + l] = val;
        }
        float2* wlp = (float2*)(sm + WL2_OFF);       // [k][n][lane]
        for (int i = tid; i < 13*5*32; i += THREADS){
            int k = i / 160, r = i - k*160;
            int n = r >> 5, l = r & 31;
            wlp[i] = make_float2(Wl[k*320 + n*64 + l], Wl[k*320 + n*64 + 32 + l]);
        }
        if (tid < 5){
            float sc = g1[tid] * rsqrtf(v1[tid] + BN_EPS);
            sm[SC1_OFF+tid] = sc; sm[SH1_OFF+tid] = b1[tid] - m1[tid]*sc;
            float s2c = g2[tid] * rsqrtf(v2[tid] + BN_EPS);
            sm[SC2_OFF+tid] = s2c; sm[SH2_OFF+tid] = b2[tid] - m2[tid]*s2c;
        }
        if (tid < 13) sm[BL_OFF+tid] = bl[tid];
    }
    __syncthreads();

    const int wid  = tid >> 5, lane = tid & 31;
    const int gid  = lane >> 2, tig = lane & 3;   // fragment coords
    const int hi_ok = (gid < 2);

    float* ws = sm + SCR_OFF + wid*WSCR;
    u32*   xh = (u32*)ws;                    // fp16x2 x rows, stride 68 u32

    const int total_tasks = (B + 1) >> 1;
    // ======================= persistent grid-stride task loop =====================
    for (int task = blockIdx.x * WARPS + wid; task < total_tasks;
         task += NBLOCKS * WARPS){

        const int b0i = task * 2;
        const int has_b1 = (b0i + 1 < B);
        const int b1i = has_b1 ? (b0i + 1) : b0i;

        // ---------------- load x (2 batches) -> fp16 A rows ----------------
        {
            const int L2 = 2*lane;
            #pragma unroll
            for (int bi = 0; bi < 2; bi++){
                const float* xg = x + (size_t)(bi ? b1i : b0i) * 1250;
                u32* xsb = xh + bi*680;
                #pragma unroll
                for (int inp = 0; inp < 2; inp++)
                    #pragma unroll
                    for (int n = 0; n < 5; n++){
                        const float* src = xg + n*250 + inp*125;
                        u32* dst = xsb + (inp*5 + n)*68;
                        dst[lane] = pkh(src[L2], src[L2+1]);
                        float c0 = (L2+64 < 125) ? src[L2+64] : 0.f;
                        float c1 = (L2+65 < 125) ? src[L2+65] : 0.f;
                        dst[lane+32] = pkh(c0, c1);
                    }
            }
        }
        __syncwarp();

        // ------- layer 1 MMA: 9 N-tiles (8 data + 1 score), K=128 in 8 k16-steps --
        float4 d1[2][9];
        #pragma unroll
        for (int bi = 0; bi < 2; bi++)
            #pragma unroll
            for (int t = 0; t < 9; t++) d1[bi][t] = make_float4(0.f, 0.f, 0.f, 0.f);
        {
            const int hi_row = hi_ok ? (gid+8)*68 : 0;
            const u32* xa0lo = xh + gid*68 + tig;
            const u32* xa0hi = xh + hi_row + tig;
            const u32* xa1lo = xa0lo + 680;
            const u32* xa1hi = xa0hi + 680;
            const uint2* bf1 = (const uint2*)(sm + BF1_OFF);
            #pragma unroll
            for (int q = 0; q < 8; q++){
                u32 a00 = xa0lo[8*q], a01 = xa0hi[8*q];
                u32 a02 = xa0lo[8*q + 4], a03 = xa0hi[8*q + 4];
                u32 a10 = xa1lo[8*q], a11r = xa1hi[8*q];
                u32 a12r = xa1lo[8*q + 4], a13 = xa1hi[8*q + 4];
                #pragma unroll
                for (int t = 0; t < 9; t++){
                    uint2 bb = bf1[(q*9 + t)*32 + lane];
                    mma16(d1[0][t], a00, a01, a02, a03, bb.x, bb.y);
                    mma16(d1[1][t], a10, a11r, a12r, a13, bb.x, bb.y);
                }
            }
        }
        __syncwarp();   // all xh reads done before H overlay writes

        // ---- layer 1: scores direct from tile 8; spill H rows (f32, stride 68) ---
        #pragma unroll
        for (int bi = 0; bi < 2; bi++){
            float2* sb = (float2*)(ws + 1360) + bi*10;
            if (tig == 0){
                sb[gid] = make_float2(d1[bi][8].x, d1[bi][8].y);
                if (hi_ok) sb[8 + gid] = make_float2(d1[bi][8].z, d1[bi][8].w);
            }
            float* hb = ws + bi*680;   // f32, stride 68
            #pragma unroll
            for (int t = 0; t < 8; t++){
                int col = 8*t + 2*tig;
                *(float2*)(hb + gid*68 + col) = make_float2(d1[bi][t].x, d1[bi][t].y);
                if (hi_ok)
                    *(float2*)(hb + (gid+8)*68 + col) = make_float2(d1[bi][t].z, d1[bi][t].w);
            }
        }
        __syncwarp();

        // ---------------- merged layer 1 softmax (20 lanes, both batches) ---------
        {
            int bb_ = lane / 10, r = lane - 10*bb_;
            int g = r / 5, j = r - 5*g;
            if (lane < 20){
                const float2* sb = (const float2*)(ws + 1360) + bb_*10;
                float* abuf = ws + 1440 + bb_*64;
                float t2j = sb[g*5 + j].y;
                float ex[5], cs = 0.f;
                #pragma unroll
                for (int i = 0; i < 5; i++){
                    float e = sb[g*5 + i].x + t2j;
                    e = (e > 0.f) ? e : ALPHA*e;
                    ex[i] = __expf(e);
                    cs += ex[i];
                }
                float rc = __fdividef(1.f, cs);
                #pragma unroll
                for (int i = 0; i < 5; i++) abuf[g*32 + i*5 + j] = ex[i]*rc;
            }
        }
        __syncwarp();

        // ---------------- apply1 + BN1 + ReLU -> h2 fp16 (stride 36) --------------
        #pragma unroll
        for (int bi = 0; bi < 2; bi++){
            const float* hb = ws + bi*680;
            const float* abuf = ws + 1440 + bi*64;
            float Ox[2][5], Oy[2][5];
            #pragma unroll
            for (int inp = 0; inp < 2; inp++)
                #pragma unroll
                for (int i = 0; i < 5; i++){ Ox[inp][i] = 0.f; Oy[inp][i] = 0.f; }
            #pragma unroll
            for (int inp = 0; inp < 2; inp++)
                #pragma unroll
                for (int j = 0; j < 5; j++){
                    float2 Hp = *(const float2*)(hb + (inp*5 + j)*68 + 2*lane);
                    #pragma unroll
                    for (int i = 0; i < 5; i++){
                        float a = abuf[inp*32 + i*5 + j];
                        Ox[inp][i] += a * Hp.x;
                        Oy[inp][i] += a * Hp.y;
                    }
                }
            __syncwarp();   // H reads complete before fp16 overlay
            u32* h2 = (u32*)(ws + bi*680);   // fp16x2, stride 36 u32
            #pragma unroll
            for (int inp = 0; inp < 2; inp++)
                #pragma unroll
                for (int n = 0; n < 5; n++){
                    float sc = sm[SC1_OFF+n], sh = sm[SH1_OFF+n];
                    float v0 = fmaxf(0.f, Ox[inp][n]*sc + sh);
                    float v1 = fmaxf(0.f, Oy[inp][n]*sc + sh);
                    h2[(inp*5 + n)*36 + lane] = pkh(v0, v1);
                }
            __syncwarp();
        }

        // ------- layer 2 MMA: 5 N-tiles (4 data + 1 score), K=64 in 4 k16-steps ---
        float4 d2[2][5];
        #pragma unroll
        for (int bi = 0; bi < 2; bi++)
            #pragma unroll
            for (int t = 0; t < 5; t++) d2[bi][t] = make_float4(0.f, 0.f, 0.f, 0.f);
        {
            const int hi_row2 = hi_ok ? (gid+8)*36 : 0;
            const u32* ha0lo = (const u32*)ws + gid*36 + tig;
            const u32* ha0hi = (const u32*)ws + hi_row2 + tig;
            const u32* ha1lo = ha0lo + 680;
            const u32* ha1hi = ha0hi + 680;
            const uint2* bf2 = (const uint2*)(sm + BF2_OFF);
            #pragma unroll
            for (int q = 0; q < 4; q++){
                u32 a00 = ha0lo[8*q], a01 = ha0hi[8*q];
                u32 a02 = ha0lo[8*q + 4], a03 = ha0hi[8*q + 4];
                u32 a10 = ha1lo[8*q], a11r = ha1hi[8*q];
                u32 a12r = ha1lo[8*q + 4], a13 = ha1hi[8*q + 4];
                #pragma unroll
                for (int t = 0; t < 5; t++){
                    uint2 bb = bf2[(q*5 + t)*32 + lane];
                    mma16(d2[0][t], a00, a01, a02, a03, bb.x, bb.y);
                    mma16(d2[1][t], a10, a11r, a12r, a13, bb.x, bb.y);
                }
            }
        }
        __syncwarp();   // h2 reads done before hh overlay

        // ---- layer 2: scores direct from tile 4; spill hh rows (f32, stride 34) --
        #pragma unroll
        for (int bi = 0; bi < 2; bi++){
            float2* sb2 = (float2*)(ws + 1400) + bi*10;
            if (tig == 0){
                sb2[gid] = make_float2(d2[bi][4].x, d2[bi][4].y);
                if (hi_ok) sb2[8 + gid] = make_float2(d2[bi][4].z, d2[bi][4].w);
            }
            float* hhb = ws + bi*680;   // f32, stride 34
            #pragma unroll
            for (int t = 0; t < 4; t++){
                int col = 8*t + 2*tig;
                *(float2*)(hhb + gid*34 + col) = make_float2(d2[bi][t].x, d2[bi][t].y);
                if (hi_ok)
                    *(float2*)(hhb + (gid+8)*34 + col) = make_float2(d2[bi][t].z, d2[bi][t].w);
            }
        }
        __syncwarp();

        // ---------------- merged layer 2 softmax (20 lanes) -----------------------
        {
            int bb_ = lane / 10, r = lane - 10*bb_;
            int g = r / 5, j = r - 5*g;
            if (lane < 20){
                const float2* sb2 = (const float2*)(ws + 1400) + bb_*10;
                float* abuf = ws + 1440 + bb_*64;
                float t2j = sb2[(1-g)*5 + j].y;
                float ex[5], cs = 0.f;
                #pragma unroll
                for (int i = 0; i < 5; i++){
                    float e = sb2[g*5 + i].x + t2j;
                    e = (e > 0.f) ? e : ALPHA*e;
                    ex[i] = __expf(e);
                    cs += ex[i];
                }
                float rc = __fdividef(1.f, cs);
                #pragma unroll
                for (int i = 0; i < 5; i++) abuf[g*32 + i*5 + j] = ex[i]*rc;
            }
        }
        __syncwarp();

        // ---------------- apply2 + BN2 + ReLU ----------------
        float y2[2][2][5];
        #pragma unroll
        for (int bi = 0; bi < 2; bi++){
            const float* hhb = ws + bi*680;
            const float* abuf = ws + 1440 + bi*64;
            float hv[2][5];
            #pragma unroll
            for (int g = 0; g < 2; g++)
                #pragma unroll
                for (int j = 0; j < 5; j++)
                    hv[g][j] = hhb[(g*5 + j)*34 + lane];
            #pragma unroll
            for (int g = 0; g < 2; g++)
                #pragma unroll
                for (int i = 0; i < 5; i++){
                    float o2 = 0.f;
                    #pragma unroll
                    for (int j = 0; j < 5; j++)
                        o2 += abuf[g*32 + i*5 + j] * hv[g][j];
                    y2[bi][g][i] = fmaxf(0.f, o2*sm[SC2_OFF+i] + sm[SH2_OFF+i]);
                }
        }

        // ---------------- final linear (shared Wl loads, both batches) ------------
        u64 f2a[5], f2b[5];
        #pragma unroll
        for (int n = 0; n < 5; n++){
            f2a[n] = pk(y2[0][0][n], y2[0][1][n]);
            f2b[n] = pk(y2[1][0][n], y2[1][1][n]);
        }
        const u64* wlp = (const u64*)(sm + WL2_OFF);
        float res0 = 0.f, res1 = 0.f;
        #pragma unroll
        for (int k = 0; k < 13; k++){
            u64 aa = 0ull, ab = 0ull;
            #pragma unroll
            for (int n = 0; n < 5; n++){
                u64 w = wlp[k*160 + n*32 + lane];
                aa = ffma2(f2a[n], w, aa);
                ab = ffma2(f2b[n], w, ab);
            }
            float r0 = wsum(hsum(aa));
            float r1 = wsum(hsum(ab));
            if (lane == k){ res0 = r0 + sm[BL_OFF+k]; res1 = r1 + sm[BL_OFF+k]; }
        }
        if (lane < 13){
            out[(size_t)b0i*13 + lane] = res0;
            if (has_b1) out[(size_t)b1i*13 + lane] = res1;
        }
        __syncwarp();   // scratch WAR: all lanes done before next task's x stores
    }
}

extern "C" void kernel_launch(void* const* d_in, const int* in_sizes, int n_in,
                              void* d_out, int out_size)
{
    const float* x   = (const float*)d_in[0];
    const float* Wt1 = (const float*)d_in[1];
    const float* a11 = (const float*)d_in[2];
    const float* a21 = (const float*)d_in[3];
    const float* g1  = (const float*)d_in[4];
    const float* b1  = (const float*)d_in[5];
    const float* m1  = (const float*)d_in[6];
    const float* v1  = (const float*)d_in[7];
    const float* Wt2 = (const float*)d_in[8];
    const float* a12 = (const float*)d_in[9];
    const float* a22 = (const float*)d_in[10];
    const float* g2  = (const float*)d_in[11];
    const float* b2  = (const float*)d_in[12];
    const float* m2  = (const float*)d_in[13];
    const float* v2  = (const float*)d_in[14];
    const float* Wl  = (const float*)d_in[15];
    const float* bl  = (const float*)d_in[16];

    int B = in_sizes[0] / 1250;
    size_t smem_bytes = (size_t)SMEM_FLOATS * sizeof(float);
    cudaFuncSetAttribute(gat_fused_kernel,
                         cudaFuncAttributeMaxDynamicSharedMemorySize, (int)smem_bytes);

    gat_fused_kernel<<<NBLOCKS, THREADS, smem_bytes>>>(
        x, Wt1, a11, a21, g1, b1, m1, v1,
        Wt2, a12, a22, g2, b2, m2, v2, Wl, bl,
        (float*)d_out, B);
}

// round 11
// speedup vs baseline: 1.5087x; 1.0164x over previous
#include <cuda_runtime.h>
#include <cuda_fp16.h>

#define ALPHA 0.2f
#define BN_EPS 1e-5f
#define THREADS 640
#define WARPS 20
#define NBLOCKS 148

typedef unsigned int u32;
typedef unsigned long long u64;

__device__ __forceinline__ u32 pkh(float a, float b){
    __half2 h = __floats2half2_rn(a, b);
    return *(u32*)&h;
}
__device__ __forceinline__ u64 ffma2(u64 a, u64 b, u64 c){
    u64 d; asm("fma.rn.f32x2 %0, %1, %2, %3;" : "=l"(d) : "l"(a), "l"(b), "l"(c)); return d;
}
__device__ __forceinline__ u64 pk(float lo, float hi){
    u64 r; asm("mov.b64 %0, {%1, %2};" : "=l"(r) : "f"(lo), "f"(hi)); return r;
}
__device__ __forceinline__ float hsum(u64 v){
    float x, y; asm("mov.b64 {%0, %1}, %2;" : "=f"(x), "=f"(y) : "l"(v)); return x + y;
}
__device__ __forceinline__ float wsum(float v){
    #pragma unroll
    for (int d = 16; d > 0; d >>= 1) v += __shfl_xor_sync(0xffffffffu, v, d);
    return v;
}
// m16n8k16 fp16 MMA, fp32 accum
__device__ __forceinline__ void mma16(float4& d, u32 a0, u32 a1, u32 a2, u32 a3, u32 b0, u32 b1){
    asm("mma.sync.aligned.m16n8k16.row.col.f32.f16.f16.f32 "
        "{%0,%1,%2,%3}, {%4,%5,%6,%7}, {%8,%9}, {%0,%1,%2,%3};"
        : "+f"(d.x), "+f"(d.y), "+f"(d.z), "+f"(d.w)
        : "r"(a0), "r"(a1), "r"(a2), "r"(a3), "r"(b0), "r"(b1));
}

// ---- shared memory layout (32-bit slots) ----
#define BF1_OFF   0        // [8 q][9 t][32 lane] uint2 fp16 B frags L1 (t=8: score cols) = 4608
#define BF2_OFF   4608     // [4 q][5 t][32] uint2 (t=4: score cols) = 1280 -> 5888
#define WL2_OFF   5888     // [13 k][5 n][32 lane] float2 = 4160 -> 10048
#define SC1_OFF   10048
#define SH1_OFF   10056
#define SC2_OFF   10064
#define SH2_OFF   10072
#define BL_OFF    10080    // 13 (pad 16) -> 10096
#define SCR_OFF   10096
// per-warp scratch (1888 slots):
//   phase 1: xh[2][10 rows][68 u32] fp16x2 x rows = 1360 at [0,1360)
//   overlay  : Ht0 fp16 col-major [0,640), Ht1 [640,1280)
//              (64 cols x 16 rows fp16, col stride 10 u32 = 20 fp16)
//   overlay2 : hh0 f32 stride34 [0,544), hh1 [640,1184)
//   SB1 [1360,1400)  SB2 [1400,1440)
//   A-attn fp16 16x16 (row stride 10 u32): A0 [1440,1600), A1 [1600,1760)
//              (zeroed once per warp; only 5x5 diag blocks written per task)
//   abuf2 f32 [1760,1888): attn2 2 x 64
#define WSCR      1888
#define SMEM_FLOATS (SCR_OFF + WARPS*WSCR)   // 47856 slots = 191424 bytes

__global__ void __launch_bounds__(THREADS, 1) gat_fused_kernel(
    const float* __restrict__ x,
    const float* __restrict__ Wt1, const float* __restrict__ a11, const float* __restrict__ a21,
    const float* __restrict__ g1,  const float* __restrict__ b1,  const float* __restrict__ m1, const float* __restrict__ v1,
    const float* __restrict__ Wt2, const float* __restrict__ a12, const float* __restrict__ a22,
    const float* __restrict__ g2,  const float* __restrict__ b2,  const float* __restrict__ m2, const float* __restrict__ v2,
    const float* __restrict__ Wl,  const float* __restrict__ bl,
    float* __restrict__ out, int B)
{
    extern __shared__ float sm[];
    const int tid = threadIdx.x;

    // -------- init phase A: folded score vectors w = W^T a (fp32, to temp smem) ----
    {
        float* wtmp = sm + SCR_OFF;
        for (int i = tid; i < 250; i += THREADS){
            int v = (i >= 125), k = i - v*125;
            const float* av = v ? a21 : a11;
            float s = 0.f;
            #pragma unroll 8
            for (int n = 0; n < 64; n++) s += av[n] * Wt1[n*125 + k];
            wtmp[v*128 + k] = s;
        }
        for (int i = tid; i < 128; i += THREADS){
            int v = (i >= 64), k = i & 63;
            const float* av = v ? a22 : a12;
            float s = 0.f;
            #pragma unroll 8
            for (int n = 0; n < 32; n++) s += av[n] * Wt2[n*64 + k];
            wtmp[256 + v*64 + k] = s;
        }
    }
    __syncthreads();

    // -------- init phase B: stage fp16 B-fragments (incl. score tiles) -------------
    {
        const float* w1a  = sm + SCR_OFF;
        const float* w2a  = sm + SCR_OFF + 128;
        const float* w1a2 = sm + SCR_OFF + 256;
        const float* w2a2 = sm + SCR_OFF + 320;

        uint2* bf1 = (uint2*)(sm + BF1_OFF);
        for (int i = tid; i < 8*9*32; i += THREADS){
            int l = i & 31, tt = i >> 5;
            int t = tt % 9, q = tt / 9;
            int k0 = 16*q + 2*(l & 3);
            uint2 val;
            if (t < 8){
                int n = 8*t + (l >> 2);
                float w0 = (k0   < 125) ? Wt1[n*125 + k0    ] : 0.f;
                float w1 = (k0+1 < 125) ? Wt1[n*125 + k0 + 1] : 0.f;
                float w8 = (k0+8 < 125) ? Wt1[n*125 + k0 + 8] : 0.f;
                float w9 = (k0+9 < 125) ? Wt1[n*125 + k0 + 9] : 0.f;
                val = make_uint2(pkh(w0, w1), pkh(w8, w9));
            } else {
                int c = l >> 2;   // col 64+c: c==0 -> w1a, c==1 -> w2a, else 0
                const float* wv = (c == 0) ? w1a : w2a;
                if (c < 2){
                    float w0 = (k0   < 125) ? wv[k0    ] : 0.f;
                    float w1 = (k0+1 < 125) ? wv[k0 + 1] : 0.f;
                    float w8 = (k0+8 < 125) ? wv[k0 + 8] : 0.f;
                    float w9 = (k0+9 < 125) ? wv[k0 + 9] : 0.f;
                    val = make_uint2(pkh(w0, w1), pkh(w8, w9));
                } else val = make_uint2(0u, 0u);
            }
            bf1[(q*9 + t)*32 + l] = val;
        }
        uint2* bf2 = (uint2*)(sm + BF2_OFF);
        for (int i = tid; i < 4*5*32; i += THREADS){
            int l = i & 31, tt = i >> 5;
            int t = tt % 5, q = tt / 5;
            int k0 = 16*q + 2*(l & 3);
            uint2 val;
            if (t < 4){
                int n = 8*t + (l >> 2);
                val = make_uint2(pkh(Wt2[n*64 + k0    ], Wt2[n*64 + k0 + 1]),
                                 pkh(Wt2[n*64 + k0 + 8], Wt2[n*64 + k0 + 9]));
            } else {
                int c = l >> 2;
                const float* wv = (c == 0) ? w1a2 : w2a2;
                if (c < 2)
                    val = make_uint2(pkh(wv[k0], wv[k0+1]), pkh(wv[k0+8], wv[k0+9]));
                else val = make_uint2(0u, 0u);
            }
            bf2[(q*5 + t)*32 + l] = val;
        }
        float2* wlp = (float2*)(sm + WL2_OFF);       // [k][n][lane]
        for (int i = tid; i < 13*5*32; i += THREADS){
            int k = i / 160, r = i - k*160;
            int n = r >> 5, l = r & 31;
            wlp[i] = make_float2(Wl[k*320 + n*64 + l], Wl[k*320 + n*64 + 32 + l]);
        }
        if (tid < 5){
            float sc = g1[tid] * rsqrtf(v1[tid] + BN_EPS);
            sm[SC1_OFF+tid] = sc; sm[SH1_OFF+tid] = b1[tid] - m1[tid]*sc;
            float s2c = g2[tid] * rsqrtf(v2[tid] + BN_EPS);
            sm[SC2_OFF+tid] = s2c; sm[SH2_OFF+tid] = b2[tid] - m2[tid]*s2c;
        }
        if (tid < 13) sm[BL_OFF+tid] = bl[tid];
    }
    __syncthreads();

    const int wid  = tid >> 5, lane = tid & 31;
    const int gid  = lane >> 2, tig = lane & 3;   // fragment coords
    const int hi_ok = (gid < 2);

    float* ws = sm + SCR_OFF + wid*WSCR;
    u32*   wsu = (u32*)ws;
    u32*   xh = wsu;                         // fp16x2 x rows, stride 68 u32

    // zero A-attn buffers once per warp (block-diag writes keep zeros elsewhere)
    for (int i = lane; i < 320; i += 32) wsu[1440 + i] = 0u;
    __syncwarp();

    const int node_lo = gid % 5;
    const int node_hi = (gid + 3) % 5;       // = (gid+8)%5

    const int total_tasks = (B + 1) >> 1;
    // ======================= persistent grid-stride task loop =====================
    for (int task = blockIdx.x * WARPS + wid; task < total_tasks;
         task += NBLOCKS * WARPS){

        const int b0i = task * 2;
        const int has_b1 = (b0i + 1 < B);
        const int b1i = has_b1 ? (b0i + 1) : b0i;

        // ---------------- load x (2 batches) -> fp16 A rows ----------------
        {
            const int L2 = 2*lane;
            #pragma unroll
            for (int bi = 0; bi < 2; bi++){
                const float* xg = x + (size_t)(bi ? b1i : b0i) * 1250;
                u32* xsb = xh + bi*680;
                #pragma unroll
                for (int inp = 0; inp < 2; inp++)
                    #pragma unroll
                    for (int n = 0; n < 5; n++){
                        const float* src = xg + n*250 + inp*125;
                        u32* dst = xsb + (inp*5 + n)*68;
                        dst[lane] = pkh(src[L2], src[L2+1]);
                        float c0 = (L2+64 < 125) ? src[L2+64] : 0.f;
                        float c1 = (L2+65 < 125) ? src[L2+65] : 0.f;
                        dst[lane+32] = pkh(c0, c1);
                    }
            }
        }
        __syncwarp();

        // ------- layer 1 MMA: 9 N-tiles (8 data + 1 score), K=128 in 8 k16-steps --
        float4 d1[2][9];
        #pragma unroll
        for (int bi = 0; bi < 2; bi++)
            #pragma unroll
            for (int t = 0; t < 9; t++) d1[bi][t] = make_float4(0.f, 0.f, 0.f, 0.f);
        {
            const int hi_row = hi_ok ? (gid+8)*68 : 0;
            const u32* xa0lo = xh + gid*68 + tig;
            const u32* xa0hi = xh + hi_row + tig;
            const u32* xa1lo = xa0lo + 680;
            const u32* xa1hi = xa0hi + 680;
            const uint2* bf1 = (const uint2*)(sm + BF1_OFF);
            #pragma unroll
            for (int q = 0; q < 8; q++){
                u32 a00 = xa0lo[8*q], a01 = xa0hi[8*q];
                u32 a02 = xa0lo[8*q + 4], a03 = xa0hi[8*q + 4];
                u32 a10 = xa1lo[8*q], a11r = xa1hi[8*q];
                u32 a12r = xa1lo[8*q + 4], a13 = xa1hi[8*q + 4];
                #pragma unroll
                for (int t = 0; t < 9; t++){
                    uint2 bb = bf1[(q*9 + t)*32 + lane];
                    mma16(d1[0][t], a00, a01, a02, a03, bb.x, bb.y);
                    mma16(d1[1][t], a10, a11r, a12r, a13, bb.x, bb.y);
                }
            }
        }
        __syncwarp();   // all xh reads done before Ht overlay writes

        // ---- layer 1: scores -> SB1; spill H as fp16 transposed (col-major) ------
        #pragma unroll
        for (int bi = 0; bi < 2; bi++){
            float2* sb = (float2*)(ws + 1360) + bi*10;
            if (tig == 0){
                sb[gid] = make_float2(d1[bi][8].x, d1[bi][8].y);
                if (hi_ok) sb[8 + gid] = make_float2(d1[bi][8].z, d1[bi][8].w);
            }
            __half* ht = (__half*)ws + bi*1280;   // col stride 20 fp16
            #pragma unroll
            for (int t = 0; t < 8; t++){
                int c = 8*t + 2*tig;
                ht[c*20 + gid]       = __float2half(d1[bi][t].x);
                ht[(c+1)*20 + gid]   = __float2half(d1[bi][t].y);
                if (hi_ok){
                    ht[c*20 + gid+8]     = __float2half(d1[bi][t].z);
                    ht[(c+1)*20 + gid+8] = __float2half(d1[bi][t].w);
                }
            }
        }
        __syncwarp();

        // ---------------- merged layer 1 softmax -> fp16 attn A-buffers -----------
        {
            int bb_ = lane / 10, r = lane - 10*bb_;
            int g = r / 5, j = r - 5*g;
            if (lane < 20){
                const float2* sb = (const float2*)(ws + 1360) + bb_*10;
                __half* ab = (__half*)ws + 2880 + bb_*320;   // row stride 20 fp16
                float t2j = sb[g*5 + j].y;
                float ex[5], cs = 0.f;
                #pragma unroll
                for (int i = 0; i < 5; i++){
                    float e = sb[g*5 + i].x + t2j;
                    e = (e > 0.f) ? e : ALPHA*e;
                    ex[i] = __expf(e);
                    cs += ex[i];
                }
                float rc = __fdividef(1.f, cs);
                #pragma unroll
                for (int i = 0; i < 5; i++)
                    ab[(g*5 + i)*20 + (g*5 + j)] = __float2half(ex[i]*rc);
            }
        }
        __syncwarp();

        // ------ per batch: apply1-MMA -> BN1/ReLU in regs -> layer 2 MMA ----------
        #pragma unroll
        for (int bi = 0; bi < 2; bi++){
            // attn A-frags (block-diag 16x16 fp16, zeros elsewhere)
            const u32* ab32 = wsu + 1440 + bi*160;
            u32 aa0 = ab32[gid*10 + tig];
            u32 aa1 = ab32[(gid+8)*10 + tig];
            u32 aa2 = ab32[gid*10 + tig + 4];
            u32 aa3 = ab32[(gid+8)*10 + tig + 4];

            // apply1: O = attn @ H   (B from Ht, 8 N-tiles, K=16 covering 10 rows)
            float4 dA[8];
            #pragma unroll
            for (int t = 0; t < 8; t++) dA[t] = make_float4(0.f, 0.f, 0.f, 0.f);
            {
                const u32* htp = wsu + bi*640;
                #pragma unroll
                for (int t = 0; t < 8; t++){
                    int c = 8*t + gid;            // Ht column (output col)
                    u32 b0 = htp[c*10 + tig];     // rows 2tig,2tig+1
                    u32 b1v = (tig == 0) ? htp[c*10 + 4] : 0u;  // rows 8,9 else zero
                    mma16(dA[t], aa0, aa1, aa2, aa3, b0, b1v);
                }
            }

            // BN1 + ReLU in regs -> fp16 A-frags -> layer 2 MMA (K=64, 4 k-steps)
            float4 d2b[5];
            #pragma unroll
            for (int t = 0; t < 5; t++) d2b[t] = make_float4(0.f, 0.f, 0.f, 0.f);
            {
                float sclo = sm[SC1_OFF + node_lo], shlo = sm[SH1_OFF + node_lo];
                float schi = sm[SC1_OFF + node_hi], shhi = sm[SH1_OFF + node_hi];
                const uint2* bf2 = (const uint2*)(sm + BF2_OFF);
                #pragma unroll
                for (int q = 0; q < 4; q++){
                    float4 lo = dA[2*q], hi = dA[2*q+1];
                    u32 a00 = pkh(fmaxf(0.f, lo.x*sclo + shlo), fmaxf(0.f, lo.y*sclo + shlo));
                    u32 a01 = pkh(fmaxf(0.f, lo.z*schi + shhi), fmaxf(0.f, lo.w*schi + shhi));
                    u32 a02 = pkh(fmaxf(0.f, hi.x*sclo + shlo), fmaxf(0.f, hi.y*sclo + shlo));
                    u32 a03 = pkh(fmaxf(0.f, hi.z*schi + shhi), fmaxf(0.f, hi.w*schi + shhi));
                    #pragma unroll
                    for (int t = 0; t < 5; t++){
                        uint2 bb = bf2[(q*5 + t)*32 + lane];
                        mma16(d2b[t], a00, a01, a02, a03, bb.x, bb.y);
                    }
                }
            }
            __syncwarp();   // all lanes' Ht reads done before hh overlay

            // scores2 -> SB2; spill hh rows (f32, stride 34)
            {
                float2* sb2 = (float2*)(ws + 1400) + bi*10;
                if (tig == 0){
                    sb2[gid] = make_float2(d2b[4].x, d2b[4].y);
                    if (hi_ok) sb2[8 + gid] = make_float2(d2b[4].z, d2b[4].w);
                }
                float* hhb = ws + bi*640;
                #pragma unroll
                for (int t = 0; t < 4; t++){
                    int col = 8*t + 2*tig;
                    *(float2*)(hhb + gid*34 + col) = make_float2(d2b[t].x, d2b[t].y);
                    if (hi_ok)
                        *(float2*)(hhb + (gid+8)*34 + col) = make_float2(d2b[t].z, d2b[t].w);
                }
            }
            __syncwarp();
        }

        // ---------------- merged layer 2 softmax (20 lanes, f32 abuf) -------------
        {
            int bb_ = lane / 10, r = lane - 10*bb_;
            int g = r / 5, j = r - 5*g;
            if (lane < 20){
                const float2* sb2 = (const float2*)(ws + 1400) + bb_*10;
                float* abuf = ws + 1760 + bb_*64;
                float t2j = sb2[(1-g)*5 + j].y;
                float ex[5], cs = 0.f;
                #pragma unroll
                for (int i = 0; i < 5; i++){
                    float e = sb2[g*5 + i].x + t2j;
                    e = (e > 0.f) ? e : ALPHA*e;
                    ex[i] = __expf(e);
                    cs += ex[i];
                }
                float rc = __fdividef(1.f, cs);
                #pragma unroll
                for (int i = 0; i < 5; i++) abuf[g*32 + i*5 + j] = ex[i]*rc;
            }
        }
        __syncwarp();

        // ---------------- apply2 + BN2 + ReLU (f32) ----------------
        float y2[2][2][5];
        #pragma unroll
        for (int bi = 0; bi < 2; bi++){
            const float* hhb = ws + bi*640;
            const float* abuf = ws + 1760 + bi*64;
            float hv[2][5];
            #pragma unroll
            for (int g = 0; g < 2; g++)
                #pragma unroll
                for (int j = 0; j < 5; j++)
                    hv[g][j] = hhb[(g*5 + j)*34 + lane];
            #pragma unroll
            for (int g = 0; g < 2; g++)
                #pragma unroll
                for (int i = 0; i < 5; i++){
                    float o2 = 0.f;
                    #pragma unroll
                    for (int j = 0; j < 5; j++)
                        o2 += abuf[g*32 + i*5 + j] * hv[g][j];
                    y2[bi][g][i] = fmaxf(0.f, o2*sm[SC2_OFF+i] + sm[SH2_OFF+i]);
                }
        }

        // ---------------- final linear (shared Wl loads, both batches) ------------
        u64 f2a[5], f2b[5];
        #pragma unroll
        for (int n = 0; n < 5; n++){
            f2a[n] = pk(y2[0][0][n], y2[0][1][n]);
            f2b[n] = pk(y2[1][0][n], y2[1][1][n]);
        }
        const u64* wlp = (const u64*)(sm + WL2_OFF);
        float res0 = 0.f, res1 = 0.f;
        #pragma unroll
        for (int k = 0; k < 13; k++){
            u64 aa = 0ull, ab = 0ull;
            #pragma unroll
            for (int n = 0; n < 5; n++){
                u64 w = wlp[k*160 + n*32 + lane];
                aa = ffma2(f2a[n], w, aa);
                ab = ffma2(f2b[n], w, ab);
            }
            float r0 = wsum(hsum(aa));
            float r1 = wsum(hsum(ab));
            if (lane == k){ res0 = r0 + sm[BL_OFF+k]; res1 = r1 + sm[BL_OFF+k]; }
        }
        if (lane < 13){
            out[(size_t)b0i*13 + lane] = res0;
            if (has_b1) out[(size_t)b1i*13 + lane] = res1;
        }
        __syncwarp();   // scratch WAR before next task's x stores
    }
}

extern "C" void kernel_launch(void* const* d_in, const int* in_sizes, int n_in,
                              void* d_out, int out_size)
{
    const float* x   = (const float*)d_in[0];
    const float* Wt1 = (const float*)d_in[1];
    const float* a11 = (const float*)d_in[2];
    const float* a21 = (const float*)d_in[3];
    const float* g1  = (const float*)d_in[4];
    const float* b1  = (const float*)d_in[5];
    const float* m1  = (const float*)d_in[6];
    const float* v1  = (const float*)d_in[7];
    const float* Wt2 = (const float*)d_in[8];
    const float* a12 = (const float*)d_in[9];
    const float* a22 = (const float*)d_in[10];
    const float* g2  = (const float*)d_in[11];
    const float* b2  = (const float*)d_in[12];
    const float* m2  = (const float*)d_in[13];
    const float* v2  = (const float*)d_in[14];
    const float* Wl  = (const float*)d_in[15];
    const float* bl  = (const float*)d_in[16];

    int B = in_sizes[0] / 1250;
    size_t smem_bytes = (size_t)SMEM_FLOATS * sizeof(float);
    cudaFuncSetAttribute(gat_fused_kernel,
                         cudaFuncAttributeMaxDynamicSharedMemorySize, (int)smem_bytes);

    gat_fused_kernel<<<NBLOCKS, THREADS, smem_bytes>>>(
        x, Wt1, a11, a21, g1, b1, m1, v1,
        Wt2, a12, a22, g2, b2, m2, v2, Wl, bl,
        (float*)d_out, B);
}

// round 12
// speedup vs baseline: 1.5176x; 1.0059x over previous
#include <cuda_runtime.h>
#include <cuda_fp16.h>

#define ALPHA 0.2f
#define BN_EPS 1e-5f
#define THREADS 768
#define WARPS 24
#define NBLOCKS 148

typedef unsigned int u32;
typedef unsigned long long u64;

__device__ __forceinline__ u32 pkh(float a, float b){
    __half2 h = __floats2half2_rn(a, b);
    return *(u32*)&h;
}
__device__ __forceinline__ u64 ffma2(u64 a, u64 b, u64 c){
    u64 d; asm("fma.rn.f32x2 %0, %1, %2, %3;" : "=l"(d) : "l"(a), "l"(b), "l"(c)); return d;
}
__device__ __forceinline__ u64 pk(float lo, float hi){
    u64 r; asm("mov.b64 %0, {%1, %2};" : "=l"(r) : "f"(lo), "f"(hi)); return r;
}
__device__ __forceinline__ float hsum(u64 v){
    float x, y; asm("mov.b64 {%0, %1}, %2;" : "=f"(x), "=f"(y) : "l"(v)); return x + y;
}
__device__ __forceinline__ float wsum(float v){
    #pragma unroll
    for (int d = 16; d > 0; d >>= 1) v += __shfl_xor_sync(0xffffffffu, v, d);
    return v;
}
// m16n8k16 fp16 MMA, fp32 accum
__device__ __forceinline__ void mma16(float4& d, u32 a0, u32 a1, u32 a2, u32 a3, u32 b0, u32 b1){
    asm("mma.sync.aligned.m16n8k16.row.col.f32.f16.f16.f32 "
        "{%0,%1,%2,%3}, {%4,%5,%6,%7}, {%8,%9}, {%0,%1,%2,%3};"
        : "+f"(d.x), "+f"(d.y), "+f"(d.z), "+f"(d.w)
        : "r"(a0), "r"(a1), "r"(a2), "r"(a3), "r"(b0), "r"(b1));
}

// ---- shared memory layout (32-bit slots) ----
#define BF1_OFF   0        // [8 q][9 t][32 lane] uint2 fp16 B frags L1 (t=8: score cols) = 4608
#define BF2_OFF   4608     // [4 q][5 t][32] uint2 (t=4: score cols) = 1280 -> 5888
#define WL2_OFF   5888     // [13 k][5 n][32 lane] float2 = 4160 -> 10048
#define SC1_OFF   10048
#define SH1_OFF   10056
#define SC2_OFF   10064
#define SH2_OFF   10072
#define BL_OFF    10080    // 13 (pad 16) -> 10096
#define SCR_OFF   10096
// per-warp scratch (1888 slots):
//   phase 1: xh[2][10 rows][68 u32] fp16x2 x rows; batch bi at [bi*680, bi*680+680)
//   overlays (per batch, after that batch's L1 MMA reads complete):
//     Ht_bi fp16 col-major at [bi*680, bi*680+640)  (64 cols, col stride 10 u32)
//     hh_bi f32 stride34 at [bi*680, bi*680+544)    (after apply1 reads Ht)
//   SB1 [1360,1400)  SB2 [1400,1440)
//   A-attn fp16 16x16 (row stride 10 u32): A0 [1440,1600), A1 [1600,1760)
//   abuf2 f32 [1760,1888): attn2 2 x 64
#define WSCR      1888
#define SMEM_FLOATS (SCR_OFF + WARPS*WSCR)   // 55408 slots = 221632 bytes

__global__ void __launch_bounds__(THREADS, 1) gat_fused_kernel(
    const float* __restrict__ x,
    const float* __restrict__ Wt1, const float* __restrict__ a11, const float* __restrict__ a21,
    const float* __restrict__ g1,  const float* __restrict__ b1,  const float* __restrict__ m1, const float* __restrict__ v1,
    const float* __restrict__ Wt2, const float* __restrict__ a12, const float* __restrict__ a22,
    const float* __restrict__ g2,  const float* __restrict__ b2,  const float* __restrict__ m2, const float* __restrict__ v2,
    const float* __restrict__ Wl,  const float* __restrict__ bl,
    float* __restrict__ out, int B)
{
    extern __shared__ float sm[];
    const int tid = threadIdx.x;

    // -------- init phase A: folded score vectors w = W^T a (fp32, to temp smem) ----
    {
        float* wtmp = sm + SCR_OFF;
        for (int i = tid; i < 250; i += THREADS){
            int v = (i >= 125), k = i - v*125;
            const float* av = v ? a21 : a11;
            float s = 0.f;
            #pragma unroll 8
            for (int n = 0; n < 64; n++) s += av[n] * Wt1[n*125 + k];
            wtmp[v*128 + k] = s;
        }
        for (int i = tid; i < 128; i += THREADS){
            int v = (i >= 64), k = i & 63;
            const float* av = v ? a22 : a12;
            float s = 0.f;
            #pragma unroll 8
            for (int n = 0; n < 32; n++) s += av[n] * Wt2[n*64 + k];
            wtmp[256 + v*64 + k] = s;
        }
    }
    __syncthreads();

    // -------- init phase B: stage fp16 B-fragments (incl. score tiles) -------------
    {
        const float* w1a  = sm + SCR_OFF;
        const float* w2a  = sm + SCR_OFF + 128;
        const float* w1a2 = sm + SCR_OFF + 256;
        const float* w2a2 = sm + SCR_OFF + 320;

        uint2* bf1 = (uint2*)(sm + BF1_OFF);
        for (int i = tid; i < 8*9*32; i += THREADS){
            int l = i & 31, tt = i >> 5;
            int t = tt % 9, q = tt / 9;
            int k0 = 16*q + 2*(l & 3);
            uint2 val;
            if (t < 8){
                int n = 8*t + (l >> 2);
                float w0 = (k0   < 125) ? Wt1[n*125 + k0    ] : 0.f;
                float w1 = (k0+1 < 125) ? Wt1[n*125 + k0 + 1] : 0.f;
                float w8 = (k0+8 < 125) ? Wt1[n*125 + k0 + 8] : 0.f;
                float w9 = (k0+9 < 125) ? Wt1[n*125 + k0 + 9] : 0.f;
                val = make_uint2(pkh(w0, w1), pkh(w8, w9));
            } else {
                int c = l >> 2;   // col 64+c: c==0 -> w1a, c==1 -> w2a, else 0
                const float* wv = (c == 0) ? w1a : w2a;
                if (c < 2){
                    float w0 = (k0   < 125) ? wv[k0    ] : 0.f;
                    float w1 = (k0+1 < 125) ? wv[k0 + 1] : 0.f;
                    float w8 = (k0+8 < 125) ? wv[k0 + 8] : 0.f;
                    float w9 = (k0+9 < 125) ? wv[k0 + 9] : 0.f;
                    val = make_uint2(pkh(w0, w1), pkh(w8, w9));
                } else val = make_uint2(0u, 0u);
            }
            bf1[(q*9 + t)*32 + l] = val;
        }
        uint2* bf2 = (uint2*)(sm + BF2_OFF);
        for (int i = tid; i < 4*5*32; i += THREADS){
            int l = i & 31, tt = i >> 5;
            int t = tt % 5, q = tt / 5;
            int k0 = 16*q + 2*(l & 3);
            uint2 val;
            if (t < 4){
                int n = 8*t + (l >> 2);
                val = make_uint2(pkh(Wt2[n*64 + k0    ], Wt2[n*64 + k0 + 1]),
                                 pkh(Wt2[n*64 + k0 + 8], Wt2[n*64 + k0 + 9]));
            } else {
                int c = l >> 2;
                const float* wv = (c == 0) ? w1a2 : w2a2;
                if (c < 2)
                    val = make_uint2(pkh(wv[k0], wv[k0+1]), pkh(wv[k0+8], wv[k0+9]));
                else val = make_uint2(0u, 0u);
            }
            bf2[(q*5 + t)*32 + l] = val;
        }
        float2* wlp = (float2*)(sm + WL2_OFF);       // [k][n][lane]
        for (int i = tid; i < 13*5*32; i += THREADS){
            int k = i / 160, r = i - k*160;
            int n = r >> 5, l = r & 31;
            wlp[i] = make_float2(Wl[k*320 + n*64 + l], Wl[k*320 + n*64 + 32 + l]);
        }
        if (tid < 5){
            float sc = g1[tid] * rsqrtf(v1[tid] + BN_EPS);
            sm[SC1_OFF+tid] = sc; sm[SH1_OFF+tid] = b1[tid] - m1[tid]*sc;
            float s2c = g2[tid] * rsqrtf(v2[tid] + BN_EPS);
            sm[SC2_OFF+tid] = s2c; sm[SH2_OFF+tid] = b2[tid] - m2[tid]*s2c;
        }
        if (tid < 13) sm[BL_OFF+tid] = bl[tid];
    }
    __syncthreads();

    const int wid  = tid >> 5, lane = tid & 31;
    const int gid  = lane >> 2, tig = lane & 3;   // fragment coords
    const int hi_ok = (gid < 2);

    float* ws = sm + SCR_OFF + wid*WSCR;
    u32*   wsu = (u32*)ws;
    u32*   xh = wsu;                         // fp16x2 x rows, stride 68 u32

    // zero A-attn buffers once per warp (block-diag writes keep zeros elsewhere)
    for (int i = lane; i < 320; i += 32) wsu[1440 + i] = 0u;
    __syncwarp();

    const int node_lo = gid % 5;
    const int node_hi = (gid + 3) % 5;       // = (gid+8)%5

    const int total_tasks = (B + 1) >> 1;
    // ======================= persistent grid-stride task loop =====================
    for (int task = blockIdx.x * WARPS + wid; task < total_tasks;
         task += NBLOCKS * WARPS){

        const int b0i = task * 2;
        const int has_b1 = (b0i + 1 < B);
        const int b1i = has_b1 ? (b0i + 1) : b0i;

        // ---------------- load x (2 batches) -> fp16 A rows ----------------
        {
            const int L2 = 2*lane;
            #pragma unroll
            for (int bi = 0; bi < 2; bi++){
                const float* xg = x + (size_t)(bi ? b1i : b0i) * 1250;
                u32* xsb = xh + bi*680;
                #pragma unroll
                for (int inp = 0; inp < 2; inp++)
                    #pragma unroll
                    for (int n = 0; n < 5; n++){
                        const float* src = xg + n*250 + inp*125;
                        u32* dst = xsb + (inp*5 + n)*68;
                        dst[lane] = pkh(src[L2], src[L2+1]);
                        float c0 = (L2+64 < 125) ? src[L2+64] : 0.f;
                        float c1 = (L2+65 < 125) ? src[L2+65] : 0.f;
                        dst[lane+32] = pkh(c0, c1);
                    }
            }
        }
        __syncwarp();

        // ------- layer 1 MMA: SEQUENTIAL per batch (d1[9] = 36 regs live) --------
        // batch bi: 9 N-tiles (8 data + 1 score), K=128 in 8 k16-steps, then
        // immediate spill of scores + Ht_bi overlaying xh[bi] (dead after MMA).
        #pragma unroll
        for (int bi = 0; bi < 2; bi++){
            float4 d1[9];
            #pragma unroll
            for (int t = 0; t < 9; t++) d1[t] = make_float4(0.f, 0.f, 0.f, 0.f);
            {
                const int hi_row = hi_ok ? (gid+8)*68 : 0;
                const u32* xlo = xh + bi*680 + gid*68 + tig;
                const u32* xhi = xh + bi*680 + hi_row + tig;
                const uint2* bf1 = (const uint2*)(sm + BF1_OFF);
                #pragma unroll
                for (int q = 0; q < 8; q++){
                    u32 a0 = xlo[8*q], a1 = xhi[8*q];
                    u32 a2 = xlo[8*q + 4], a3 = xhi[8*q + 4];
                    #pragma unroll
                    for (int t = 0; t < 9; t++){
                        uint2 bb = bf1[(q*9 + t)*32 + lane];
                        mma16(d1[t], a0, a1, a2, a3, bb.x, bb.y);
                    }
                }
            }
            __syncwarp();   // all lanes' xh[bi] reads done before Ht_bi overlay

            // scores -> SB1; spill H as fp16 transposed (col-major, stride 20 fp16)
            float2* sb = (float2*)(ws + 1360) + bi*10;
            if (tig == 0){
                sb[gid] = make_float2(d1[8].x, d1[8].y);
                if (hi_ok) sb[8 + gid] = make_float2(d1[8].z, d1[8].w);
            }
            __half* ht = (__half*)(wsu + bi*680);
            #pragma unroll
            for (int t = 0; t < 8; t++){
                int c = 8*t + 2*tig;
                ht[c*20 + gid]       = __float2half(d1[t].x);
                ht[(c+1)*20 + gid]   = __float2half(d1[t].y);
                if (hi_ok){
                    ht[c*20 + gid+8]     = __float2half(d1[t].z);
                    ht[(c+1)*20 + gid+8] = __float2half(d1[t].w);
                }
            }
        }
        __syncwarp();

        // ---------------- merged layer 1 softmax -> fp16 attn A-buffers -----------
        {
            int bb_ = lane / 10, r = lane - 10*bb_;
            int g = r / 5, j = r - 5*g;
            if (lane < 20){
                const float2* sb = (const float2*)(ws + 1360) + bb_*10;
                __half* ab = (__half*)(wsu + 1440) + bb_*320;   // row stride 20 fp16
                float t2j = sb[g*5 + j].y;
                float ex[5], cs = 0.f;
                #pragma unroll
                for (int i = 0; i < 5; i++){
                    float e = sb[g*5 + i].x + t2j;
                    e = (e > 0.f) ? e : ALPHA*e;
                    ex[i] = __expf(e);
                    cs += ex[i];
                }
                float rc = __fdividef(1.f, cs);
                #pragma unroll
                for (int i = 0; i < 5; i++)
                    ab[(g*5 + i)*20 + (g*5 + j)] = __float2half(ex[i]*rc);
            }
        }
        __syncwarp();

        // ------ per batch: apply1-MMA -> BN1/ReLU in regs -> layer 2 MMA ----------
        #pragma unroll
        for (int bi = 0; bi < 2; bi++){
            // attn A-frags (block-diag 16x16 fp16, zeros elsewhere)
            const u32* ab32 = wsu + 1440 + bi*160;
            u32 aa0 = ab32[gid*10 + tig];
            u32 aa1 = ab32[(gid+8)*10 + tig];
            u32 aa2 = ab32[gid*10 + tig + 4];
            u32 aa3 = ab32[(gid+8)*10 + tig + 4];

            // apply1: O = attn @ H   (B from Ht, 8 N-tiles, K=16 covering 10 rows)
            float4 dA[8];
            #pragma unroll
            for (int t = 0; t < 8; t++) dA[t] = make_float4(0.f, 0.f, 0.f, 0.f);
            {
                const u32* htp = wsu + bi*680;
                #pragma unroll
                for (int t = 0; t < 8; t++){
                    int c = 8*t + gid;            // Ht column (output col)
                    u32 b0 = htp[c*10 + tig];     // rows 2tig,2tig+1
                    u32 b1v = (tig == 0) ? htp[c*10 + 4] : 0u;  // rows 8,9 else zero
                    mma16(dA[t], aa0, aa1, aa2, aa3, b0, b1v);
                }
            }

            // BN1 + ReLU in regs -> fp16 A-frags -> layer 2 MMA (K=64, 4 k-steps)
            float4 d2b[5];
            #pragma unroll
            for (int t = 0; t < 5; t++) d2b[t] = make_float4(0.f, 0.f, 0.f, 0.f);
            {
                float sclo = sm[SC1_OFF + node_lo], shlo = sm[SH1_OFF + node_lo];
                float schi = sm[SC1_OFF + node_hi], shhi = sm[SH1_OFF + node_hi];
                const uint2* bf2 = (const uint2*)(sm + BF2_OFF);
                #pragma unroll
                for (int q = 0; q < 4; q++){
                    float4 lo = dA[2*q], hi = dA[2*q+1];
                    u32 a00 = pkh(fmaxf(0.f, lo.x*sclo + shlo), fmaxf(0.f, lo.y*sclo + shlo));
                    u32 a01 = pkh(fmaxf(0.f, lo.z*schi + shhi), fmaxf(0.f, lo.w*schi + shhi));
                    u32 a02 = pkh(fmaxf(0.f, hi.x*sclo + shlo), fmaxf(0.f, hi.y*sclo + shlo));
                    u32 a03 = pkh(fmaxf(0.f, hi.z*schi + shhi), fmaxf(0.f, hi.w*schi + shhi));
                    #pragma unroll
                    for (int t = 0; t < 5; t++){
                        uint2 bb = bf2[(q*5 + t)*32 + lane];
                        mma16(d2b[t], a00, a01, a02, a03, bb.x, bb.y);
                    }
                }
            }
            __syncwarp();   // all lanes' Ht reads done before hh overlay

            // scores2 -> SB2; spill hh rows (f32, stride 34)
            {
                float2* sb2 = (float2*)(ws + 1400) + bi*10;
                if (tig == 0){
                    sb2[gid] = make_float2(d2b[4].x, d2b[4].y);
                    if (hi_ok) sb2[8 + gid] = make_float2(d2b[4].z, d2b[4].w);
                }
                float* hhb = ws + bi*680;
                #pragma unroll
                for (int t = 0; t < 4; t++){
                    int col = 8*t + 2*tig;
                    *(float2*)(hhb + gid*34 + col) = make_float2(d2b[t].x, d2b[t].y);
                    if (hi_ok)
                        *(float2*)(hhb + (gid+8)*34 + col) = make_float2(d2b[t].z, d2b[t].w);
                }
            }
            __syncwarp();
        }

        // ---------------- merged layer 2 softmax (20 lanes, f32 abuf) -------------
        {
            int bb_ = lane / 10, r = lane - 10*bb_;
            int g = r / 5, j = r - 5*g;
            if (lane < 20){
                const float2* sb2 = (const float2*)(ws + 1400) + bb_*10;
                float* abuf = ws + 1760 + bb_*64;
                float t2j = sb2[(1-g)*5 + j].y;
                float ex[5], cs = 0.f;
                #pragma unroll
                for (int i = 0; i < 5; i++){
                    float e = sb2[g*5 + i].x + t2j;
                    e = (e > 0.f) ? e : ALPHA*e;
                    ex[i] = __expf(e);
                    cs += ex[i];
                }
                float rc = __fdividef(1.f, cs);
                #pragma unroll
                for (int i = 0; i < 5; i++) abuf[g*32 + i*5 + j] = ex[i]*rc;
            }
        }
        __syncwarp();

        // ---------------- apply2 + BN2 + ReLU (f32) ----------------
        float y2[2][2][5];
        #pragma unroll
        for (int bi = 0; bi < 2; bi++){
            const float* hhb = ws + bi*680;
            const float* abuf = ws + 1760 + bi*64;
            float hv[2][5];
            #pragma unroll
            for (int g = 0; g < 2; g++)
                #pragma unroll
                for (int j = 0; j < 5; j++)
                    hv[g][j] = hhb[(g*5 + j)*34 + lane];
            #pragma unroll
            for (int g = 0; g < 2; g++)
                #pragma unroll
                for (int i = 0; i < 5; i++){
                    float o2 = 0.f;
                    #pragma unroll
                    for (int j = 0; j < 5; j++)
                        o2 += abuf[g*32 + i*5 + j] * hv[g][j];
                    y2[bi][g][i] = fmaxf(0.f, o2*sm[SC2_OFF+i] + sm[SH2_OFF+i]);
                }
        }

        // ---------------- final linear (shared Wl loads, both batches) ------------
        u64 f2a[5], f2b[5];
        #pragma unroll
        for (int n = 0; n < 5; n++){
            f2a[n] = pk(y2[0][0][n], y2[0][1][n]);
            f2b[n] = pk(y2[1][0][n], y2[1][1][n]);
        }
        const u64* wlp = (const u64*)(sm + WL2_OFF);
        float res0 = 0.f, res1 = 0.f;
        #pragma unroll
        for (int k = 0; k < 13; k++){
            u64 aa = 0ull, ab = 0ull;
            #pragma unroll
            for (int n = 0; n < 5; n++){
                u64 w = wlp[k*160 + n*32 + lane];
                aa = ffma2(f2a[n], w, aa);
                ab = ffma2(f2b[n], w, ab);
            }
            float r0 = wsum(hsum(aa));
            float r1 = wsum(hsum(ab));
            if (lane == k){ res0 = r0 + sm[BL_OFF+k]; res1 = r1 + sm[BL_OFF+k]; }
        }
        if (lane < 13){
            out[(size_t)b0i*13 + lane] = res0;
            if (has_b1) out[(size_t)b1i*13 + lane] = res1;
        }
        __syncwarp();   // scratch WAR before next task's x stores
    }
}

extern "C" void kernel_launch(void* const* d_in, const int* in_sizes, int n_in,
                              void* d_out, int out_size)
{
    const float* x   = (const float*)d_in[0];
    const float* Wt1 = (const float*)d_in[1];
    const float* a11 = (const float*)d_in[2];
    const float* a21 = (const float*)d_in[3];
    const float* g1  = (const float*)d_in[4];
    const float* b1  = (const float*)d_in[5];
    const float* m1  = (const float*)d_in[6];
    const float* v1  = (const float*)d_in[7];
    const float* Wt2 = (const float*)d_in[8];
    const float* a12 = (const float*)d_in[9];
    const float* a22 = (const float*)d_in[10];
    const float* g2  = (const float*)d_in[11];
    const float* b2  = (const float*)d_in[12];
    const float* m2  = (const float*)d_in[13];
    const float* v2  = (const float*)d_in[14];
    const float* Wl  = (const float*)d_in[15];
    const float* bl  = (const float*)d_in[16];

    int B = in_sizes[0] / 1250;
    size_t smem_bytes = (size_t)SMEM_FLOATS * sizeof(float);
    cudaFuncSetAttribute(gat_fused_kernel,
                         cudaFuncAttributeMaxDynamicSharedMemorySize, (int)smem_bytes);

    gat_fused_kernel<<<NBLOCKS, THREADS, smem_bytes>>>(
        x, Wt1, a11, a21, g1, b1, m1, v1,
        Wt2, a12, a22, g2, b2, m2, v2, Wl, bl,
        (float*)d_out, B);
}

// round 13
// speedup vs baseline: 1.5328x; 1.0101x over previous
#include <cuda_runtime.h>
#include <cuda_fp16.h>

#define ALPHA 0.2f
#define BN_EPS 1e-5f
#define THREADS 768
#define WARPS 24
#define NBLOCKS 148

typedef unsigned int u32;
typedef unsigned long long u64;

__device__ __forceinline__ u32 pkh(float a, float b){
    __half2 h = __floats2half2_rn(a, b);
    return *(u32*)&h;
}
__device__ __forceinline__ u64 ffma2(u64 a, u64 b, u64 c){
    u64 d; asm("fma.rn.f32x2 %0, %1, %2, %3;" : "=l"(d) : "l"(a), "l"(b), "l"(c)); return d;
}
__device__ __forceinline__ u64 pk(float lo, float hi){
    u64 r; asm("mov.b64 %0, {%1, %2};" : "=l"(r) : "f"(lo), "f"(hi)); return r;
}
__device__ __forceinline__ float hsum(u64 v){
    float x, y; asm("mov.b64 {%0, %1}, %2;" : "=f"(x), "=f"(y) : "l"(v)); return x + y;
}
__device__ __forceinline__ u32 smem_u32(const void* p){
    u32 r; asm("{ .reg .u64 t; cvta.to.shared.u64 t, %1; cvt.u32.u64 %0, t; }" : "=r"(r) : "l"(p));
    return r;
}
__device__ __forceinline__ void ldsm4(u32& r0, u32& r1, u32& r2, u32& r3, u32 addr){
    asm volatile("ldmatrix.sync.aligned.m8n8.x4.shared.b16 {%0,%1,%2,%3}, [%4];"
                 : "=r"(r0), "=r"(r1), "=r"(r2), "=r"(r3) : "r"(addr));
}
__device__ __forceinline__ void ldsm2(u32& r0, u32& r1, u32 addr){
    asm volatile("ldmatrix.sync.aligned.m8n8.x2.shared.b16 {%0,%1}, [%2];"
                 : "=r"(r0), "=r"(r1) : "r"(addr));
}
// m16n8k16 fp16 MMA, fp32 accum
__device__ __forceinline__ void mma16(float4& d, u32 a0, u32 a1, u32 a2, u32 a3, u32 b0, u32 b1){
    asm("mma.sync.aligned.m16n8k16.row.col.f32.f16.f16.f32 "
        "{%0,%1,%2,%3}, {%4,%5,%6,%7}, {%8,%9}, {%0,%1,%2,%3};"
        : "+f"(d.x), "+f"(d.y), "+f"(d.z), "+f"(d.w)
        : "r"(a0), "r"(a1), "r"(a2), "r"(a3), "r"(b0), "r"(b1));
}

// ---- shared memory layout (32-bit slots) ----
// bf1: ldmatrix layout [8 q][9 t][2 h] 8x8 fp16 matrices (128B each, row=n, 8 k's)
#define BF1_OFF   0        // 8*18*32 = 4608 slots
#define BF2_OFF   4608     // [4 q][5 t][2 h] matrices = 4*10*32 = 1280 -> 5888
#define WL2_OFF   5888     // [13 k][5 n][32 lane] float2 = 4160 -> 10048
#define SC1_OFF   10048
#define SH1_OFF   10056
#define SC2_OFF   10064
#define SH2_OFF   10072
#define BL_OFF    10080    // 13 (pad 16) -> 10096
#define SCR_OFF   10096
// per-warp scratch (1888 slots):
//   phase 1: xh[2][10 rows][68 u32] fp16x2 x rows; batch bi at [bi*680, +680)
//   overlays: Ht_bi fp16 col-major at [bi*680, +640); hh_bi f32 stride34;
//             red[26][36] f32 at [0,936) for final reduction (after hh reads)
//   SB1 [1360,1400)  SB2 [1400,1440)
//   A-attn fp16 16x16 (row stride 10 u32): A0 [1440,1600), A1 [1600,1760)
//   abuf2 f32 [1760,1888)
#define WSCR      1888
#define SMEM_FLOATS (SCR_OFF + WARPS*WSCR)   // 55408 slots = 221632 bytes

__global__ void __launch_bounds__(THREADS, 1) gat_fused_kernel(
    const float* __restrict__ x,
    const float* __restrict__ Wt1, const float* __restrict__ a11, const float* __restrict__ a21,
    const float* __restrict__ g1,  const float* __restrict__ b1,  const float* __restrict__ m1, const float* __restrict__ v1,
    const float* __restrict__ Wt2, const float* __restrict__ a12, const float* __restrict__ a22,
    const float* __restrict__ g2,  const float* __restrict__ b2,  const float* __restrict__ m2, const float* __restrict__ v2,
    const float* __restrict__ Wl,  const float* __restrict__ bl,
    float* __restrict__ out, int B)
{
    extern __shared__ float sm[];
    const int tid = threadIdx.x;

    // -------- init phase A: folded score vectors w = W^T a (fp32, to temp smem) ----
    {
        float* wtmp = sm + SCR_OFF;
        for (int i = tid; i < 250; i += THREADS){
            int v = (i >= 125), k = i - v*125;
            const float* av = v ? a21 : a11;
            float s = 0.f;
            #pragma unroll 8
            for (int n = 0; n < 64; n++) s += av[n] * Wt1[n*125 + k];
            wtmp[v*128 + k] = s;
        }
        for (int i = tid; i < 128; i += THREADS){
            int v = (i >= 64), k = i & 63;
            const float* av = v ? a22 : a12;
            float s = 0.f;
            #pragma unroll 8
            for (int n = 0; n < 32; n++) s += av[n] * Wt2[n*64 + k];
            wtmp[256 + v*64 + k] = s;
        }
    }
    __syncthreads();

    // -------- init phase B: stage fp16 B-matrices in ldmatrix layout ---------------
    {
        const float* w1a  = sm + SCR_OFF;
        const float* w2a  = sm + SCR_OFF + 128;
        const float* w1a2 = sm + SCR_OFF + 256;
        const float* w2a2 = sm + SCR_OFF + 320;

        // bf1: slot i -> q = i/576, u = (i%576)/32 (u = t*2+h), r = (i>>2)&7, j = i&3
        u32* bf1 = (u32*)(sm + BF1_OFF);
        for (int i = tid; i < 4608; i += THREADS){
            int j = i & 3, r = (i >> 2) & 7;
            int u = (i >> 5) % 18, q = i / 576;
            int t = u >> 1, h = u & 1;
            int k = 16*q + 8*h + 2*j;
            u32 val;
            if (t < 8){
                int n = 8*t + r;
                float w0 = (k   < 125) ? Wt1[n*125 + k    ] : 0.f;
                float w1 = (k+1 < 125) ? Wt1[n*125 + k + 1] : 0.f;
                val = pkh(w0, w1);
            } else {
                const float* wv = (r == 0) ? w1a : w2a;
                if (r < 2){
                    float w0 = (k   < 125) ? wv[k    ] : 0.f;
                    float w1 = (k+1 < 125) ? wv[k + 1] : 0.f;
                    val = pkh(w0, w1);
                } else val = 0u;
            }
            bf1[i] = val;
        }
        // bf2: slot i -> q = i/320, u = (i%320)/32 (u = t*2+h), r, j
        u32* bf2 = (u32*)(sm + BF2_OFF);
        for (int i = tid; i < 1280; i += THREADS){
            int j = i & 3, r = (i >> 2) & 7;
            int u = (i >> 5) % 10, q = i / 320;
            int t = u >> 1, h = u & 1;
            int k = 16*q + 8*h + 2*j;
            u32 val;
            if (t < 4){
                int n = 8*t + r;
                val = pkh(Wt2[n*64 + k], Wt2[n*64 + k + 1]);
            } else {
                const float* wv = (r == 0) ? w1a2 : w2a2;
                val = (r < 2) ? pkh(wv[k], wv[k+1]) : 0u;
            }
            bf2[i] = val;
        }
        float2* wlp = (float2*)(sm + WL2_OFF);       // [k][n][lane]
        for (int i = tid; i < 13*5*32; i += THREADS){
            int k = i / 160, r = i - k*160;
            int n = r >> 5, l = r & 31;
            wlp[i] = make_float2(Wl[k*320 + n*64 + l], Wl[k*320 + n*64 + 32 + l]);
        }
        if (tid < 5){
            float sc = g1[tid] * rsqrtf(v1[tid] + BN_EPS);
            sm[SC1_OFF+tid] = sc; sm[SH1_OFF+tid] = b1[tid] - m1[tid]*sc;
            float s2c = g2[tid] * rsqrtf(v2[tid] + BN_EPS);
            sm[SC2_OFF+tid] = s2c; sm[SH2_OFF+tid] = b2[tid] - m2[tid]*s2c;
        }
        if (tid < 13) sm[BL_OFF+tid] = bl[tid];
    }
    __syncthreads();

    const int wid  = tid >> 5, lane = tid & 31;
    const int gid  = lane >> 2, tig = lane & 3;   // fragment coords
    const int hi_ok = (gid < 2);
    const int lmat = lane >> 3, lrow = lane & 7;  // ldmatrix address coords

    float* ws = sm + SCR_OFF + wid*WSCR;
    u32*   wsu = (u32*)ws;
    u32*   xh = wsu;                         // fp16x2 x rows, stride 68 u32

    // per-lane ldmatrix base addresses (bytes, shared space)
    const u32 laneoff = (u32)(lmat*128 + lrow*16);
    const u32 bf1s = smem_u32(sm + BF1_OFF) + laneoff;
    const u32 bf2s = smem_u32(sm + BF2_OFF) + laneoff;

    // zero A-attn buffers once per warp (block-diag writes keep zeros elsewhere)
    for (int i = lane; i < 320; i += 32) wsu[1440 + i] = 0u;
    __syncwarp();

    const int node_lo = gid % 5;
    const int node_hi = (gid + 3) % 5;       // = (gid+8)%5

    const int total_tasks = (B + 1) >> 1;
    // ======================= persistent grid-stride task loop =====================
    for (int task = blockIdx.x * WARPS + wid; task < total_tasks;
         task += NBLOCKS * WARPS){

        const int b0i = task * 2;
        const int has_b1 = (b0i + 1 < B);
        const int b1i = has_b1 ? (b0i + 1) : b0i;

        // ---------------- load x (2 batches) -> fp16 A rows ----------------
        {
            const int L2 = 2*lane;
            #pragma unroll
            for (int bi = 0; bi < 2; bi++){
                const float* xg = x + (size_t)(bi ? b1i : b0i) * 1250;
                u32* xsb = xh + bi*680;
                #pragma unroll
                for (int inp = 0; inp < 2; inp++)
                    #pragma unroll
                    for (int n = 0; n < 5; n++){
                        const float* src = xg + n*250 + inp*125;
                        u32* dst = xsb + (inp*5 + n)*68;
                        dst[lane] = pkh(src[L2], src[L2+1]);
                        float c0 = (L2+64 < 125) ? src[L2+64] : 0.f;
                        float c1 = (L2+65 < 125) ? src[L2+65] : 0.f;
                        dst[lane+32] = pkh(c0, c1);
                    }
            }
        }
        __syncwarp();

        // ------- layer 1 MMA: sequential per batch, B-frags via ldmatrix ---------
        #pragma unroll
        for (int bi = 0; bi < 2; bi++){
            float4 d1[9];
            #pragma unroll
            for (int t = 0; t < 9; t++) d1[t] = make_float4(0.f, 0.f, 0.f, 0.f);
            {
                const int hi_row = hi_ok ? (gid+8)*68 : 0;
                const u32* xlo = xh + bi*680 + gid*68 + tig;
                const u32* xhi = xh + bi*680 + hi_row + tig;
                #pragma unroll
                for (int q = 0; q < 8; q++){
                    u32 a0 = xlo[8*q], a1 = xhi[8*q];
                    u32 a2 = xlo[8*q + 4], a3 = xhi[8*q + 4];
                    u32 bq = bf1s + q*2304;   // 576 u32 * 4B per q
                    #pragma unroll
                    for (int g = 0; g < 4; g++){
                        u32 r0, r1, r2, r3;
                        ldsm4(r0, r1, r2, r3, bq + g*512);
                        mma16(d1[2*g],   a0, a1, a2, a3, r0, r1);
                        mma16(d1[2*g+1], a0, a1, a2, a3, r2, r3);
                    }
                    u32 s0, s1;
                    ldsm2(s0, s1, bq + 2048);
                    mma16(d1[8], a0, a1, a2, a3, s0, s1);
                }
            }
            __syncwarp();   // all lanes' xh[bi] reads done before Ht_bi overlay

            // scores -> SB1; spill H as fp16 transposed (col-major, stride 20 fp16)
            float2* sb = (float2*)(ws + 1360) + bi*10;
            if (tig == 0){
                sb[gid] = make_float2(d1[8].x, d1[8].y);
                if (hi_ok) sb[8 + gid] = make_float2(d1[8].z, d1[8].w);
            }
            __half* ht = (__half*)(wsu + bi*680);
            #pragma unroll
            for (int t = 0; t < 8; t++){
                int c = 8*t + 2*tig;
                ht[c*20 + gid]       = __float2half(d1[t].x);
                ht[(c+1)*20 + gid]   = __float2half(d1[t].y);
                if (hi_ok){
                    ht[c*20 + gid+8]     = __float2half(d1[t].z);
                    ht[(c+1)*20 + gid+8] = __float2half(d1[t].w);
                }
            }
        }
        __syncwarp();

        // ---------------- merged layer 1 softmax -> fp16 attn A-buffers -----------
        {
            int bb_ = lane / 10, r = lane - 10*bb_;
            int g = r / 5, j = r - 5*g;
            if (lane < 20){
                const float2* sb = (const float2*)(ws + 1360) + bb_*10;
                __half* ab = (__half*)(wsu + 1440) + bb_*320;   // row stride 20 fp16
                float t2j = sb[g*5 + j].y;
                float ex[5], cs = 0.f;
                #pragma unroll
                for (int i = 0; i < 5; i++){
                    float e = sb[g*5 + i].x + t2j;
                    e = (e > 0.f) ? e : ALPHA*e;
                    ex[i] = __expf(e);
                    cs += ex[i];
                }
                float rc = __fdividef(1.f, cs);
                #pragma unroll
                for (int i = 0; i < 5; i++)
                    ab[(g*5 + i)*20 + (g*5 + j)] = __float2half(ex[i]*rc);
            }
        }
        __syncwarp();

        // ------ per batch: apply1-MMA -> BN1/ReLU in regs -> layer 2 MMA ----------
        #pragma unroll
        for (int bi = 0; bi < 2; bi++){
            // attn A-frags (block-diag 16x16 fp16, zeros elsewhere)
            const u32* ab32 = wsu + 1440 + bi*160;
            u32 aa0 = ab32[gid*10 + tig];
            u32 aa1 = ab32[(gid+8)*10 + tig];
            u32 aa2 = ab32[gid*10 + tig + 4];
            u32 aa3 = ab32[(gid+8)*10 + tig + 4];

            // apply1: O = attn @ H   (B from Ht, 8 N-tiles, K=16 covering 10 rows)
            float4 dA[8];
            #pragma unroll
            for (int t = 0; t < 8; t++) dA[t] = make_float4(0.f, 0.f, 0.f, 0.f);
            {
                const u32* htp = wsu + bi*680;
                #pragma unroll
                for (int t = 0; t < 8; t++){
                    int c = 8*t + gid;            // Ht column (output col)
                    u32 b0 = htp[c*10 + tig];     // rows 2tig,2tig+1
                    u32 b1v = (tig == 0) ? htp[c*10 + 4] : 0u;  // rows 8,9 else zero
                    mma16(dA[t], aa0, aa1, aa2, aa3, b0, b1v);
                }
            }

            // BN1 + ReLU in regs -> fp16 A-frags -> layer 2 MMA (ldmatrix B-frags)
            float4 d2b[5];
            #pragma unroll
            for (int t = 0; t < 5; t++) d2b[t] = make_float4(0.f, 0.f, 0.f, 0.f);
            {
                float sclo = sm[SC1_OFF + node_lo], shlo = sm[SH1_OFF + node_lo];
                float schi = sm[SC1_OFF + node_hi], shhi = sm[SH1_OFF + node_hi];
                #pragma unroll
                for (int q = 0; q < 4; q++){
                    float4 lo = dA[2*q], hi = dA[2*q+1];
                    u32 a00 = pkh(fmaxf(0.f, lo.x*sclo + shlo), fmaxf(0.f, lo.y*sclo + shlo));
                    u32 a01 = pkh(fmaxf(0.f, lo.z*schi + shhi), fmaxf(0.f, lo.w*schi + shhi));
                    u32 a02 = pkh(fmaxf(0.f, hi.x*sclo + shlo), fmaxf(0.f, hi.y*sclo + shlo));
                    u32 a03 = pkh(fmaxf(0.f, hi.z*schi + shhi), fmaxf(0.f, hi.w*schi + shhi));
                    u32 bq = bf2s + q*1280;   // 320 u32 * 4B per q
                    #pragma unroll
                    for (int g = 0; g < 2; g++){
                        u32 r0, r1, r2, r3;
                        ldsm4(r0, r1, r2, r3, bq + g*512);
                        mma16(d2b[2*g],   a00, a01, a02, a03, r0, r1);
                        mma16(d2b[2*g+1], a00, a01, a02, a03, r2, r3);
                    }
                    u32 s0, s1;
                    ldsm2(s0, s1, bq + 1024);
                    mma16(d2b[4], a00, a01, a02, a03, s0, s1);
                }
            }
            __syncwarp();   // all lanes' Ht reads done before hh overlay

            // scores2 -> SB2; spill hh rows (f32, stride 34)
            {
                float2* sb2 = (float2*)(ws + 1400) + bi*10;
                if (tig == 0){
                    sb2[gid] = make_float2(d2b[4].x, d2b[4].y);
                    if (hi_ok) sb2[8 + gid] = make_float2(d2b[4].z, d2b[4].w);
                }
                float* hhb = ws + bi*680;
                #pragma unroll
                for (int t = 0; t < 4; t++){
                    int col = 8*t + 2*tig;
                    *(float2*)(hhb + gid*34 + col) = make_float2(d2b[t].x, d2b[t].y);
                    if (hi_ok)
                        *(float2*)(hhb + (gid+8)*34 + col) = make_float2(d2b[t].z, d2b[t].w);
                }
            }
            __syncwarp();
        }

        // ---------------- merged layer 2 softmax (20 lanes, f32 abuf) -------------
        {
            int bb_ = lane / 10, r = lane - 10*bb_;
            int g = r / 5, j = r - 5*g;
            if (lane < 20){
                const float2* sb2 = (const float2*)(ws + 1400) + bb_*10;
                float* abuf = ws + 1760 + bb_*64;
                float t2j = sb2[(1-g)*5 + j].y;
                float ex[5], cs = 0.f;
                #pragma unroll
                for (int i = 0; i < 5; i++){
                    float e = sb2[g*5 + i].x + t2j;
                    e = (e > 0.f) ? e : ALPHA*e;
                    ex[i] = __expf(e);
                    cs += ex[i];
                }
                float rc = __fdividef(1.f, cs);
                #pragma unroll
                for (int i = 0; i < 5; i++) abuf[g*32 + i*5 + j] = ex[i]*rc;
            }
        }
        __syncwarp();

        // ---------------- apply2 + BN2 + ReLU (f32) ----------------
        float y2[2][2][5];
        #pragma unroll
        for (int bi = 0; bi < 2; bi++){
            const float* hhb = ws + bi*680;
            const float* abuf = ws + 1760 + bi*64;
            float hv[2][5];
            #pragma unroll
            for (int g = 0; g < 2; g++)
                #pragma unroll
                for (int j = 0; j < 5; j++)
                    hv[g][j] = hhb[(g*5 + j)*34 + lane];
            #pragma unroll
            for (int g = 0; g < 2; g++)
                #pragma unroll
                for (int i = 0; i < 5; i++){
                    float o2 = 0.f;
                    #pragma unroll
                    for (int j = 0; j < 5; j++)
                        o2 += abuf[g*32 + i*5 + j] * hv[g][j];
                    y2[bi][g][i] = fmaxf(0.f, o2*sm[SC2_OFF+i] + sm[SH2_OFF+i]);
                }
        }
        __syncwarp();   // hh reads done before red overlay

        // ------- final linear: partials to smem (stride 36), 26-lane row sums -----
        u64 f2a[5], f2b[5];
        #pragma unroll
        for (int n = 0; n < 5; n++){
            f2a[n] = pk(y2[0][0][n], y2[0][1][n]);
            f2b[n] = pk(y2[1][0][n], y2[1][1][n]);
        }
        const u64* wlp = (const u64*)(sm + WL2_OFF);
        #pragma unroll
        for (int k = 0; k < 13; k++){
            u64 aa = 0ull, ab = 0ull;
            #pragma unroll
            for (int n = 0; n < 5; n++){
                u64 w = wlp[k*160 + n*32 + lane];
                aa = ffma2(f2a[n], w, aa);
                ab = ffma2(f2b[n], w, ab);
            }
            ws[k*36 + lane]        = hsum(aa);
            ws[(13 + k)*36 + lane] = hsum(ab);
        }
        __syncwarp();
        if (lane < 26){
            const float4* rp = (const float4*)(ws + lane*36);
            float s = 0.f;
            #pragma unroll
            for (int j = 0; j < 8; j++){
                float4 v = rp[j];
                s += (v.x + v.y) + (v.z + v.w);
            }
            int k = (lane < 13) ? lane : lane - 13;
            float res = s + sm[BL_OFF + k];
            if (lane < 13)       out[(size_t)b0i*13 + lane] = res;
            else if (has_b1)     out[(size_t)b1i*13 + k]    = res;
        }
        __syncwarp();   // scratch WAR before next task's x stores
    }
}

extern "C" void kernel_launch(void* const* d_in, const int* in_sizes, int n_in,
                              void* d_out, int out_size)
{
    const float* x   = (const float*)d_in[0];
    const float* Wt1 = (const float*)d_in[1];
    const float* a11 = (const float*)d_in[2];
    const float* a21 = (const float*)d_in[3];
    const float* g1  = (const float*)d_in[4];
    const float* b1  = (const float*)d_in[5];
    const float* m1  = (const float*)d_in[6];
    const float* v1  = (const float*)d_in[7];
    const float* Wt2 = (const float*)d_in[8];
    const float* a12 = (const float*)d_in[9];
    const float* a22 = (const float*)d_in[10];
    const float* g2  = (const float*)d_in[11];
    const float* b2  = (const float*)d_in[12];
    const float* m2  = (const float*)d_in[13];
    const float* v2  = (const float*)d_in[14];
    const float* Wl  = (const float*)d_in[15];
    const float* bl  = (const float*)d_in[16];

    int B = in_sizes[0] / 1250;
    size_t smem_bytes = (size_t)SMEM_FLOATS * sizeof(float);
    cudaFuncSetAttribute(gat_fused_kernel,
                         cudaFuncAttributeMaxDynamicSharedMemorySize, (int)smem_bytes);

    gat_fused_kernel<<<NBLOCKS, THREADS, smem_bytes>>>(
        x, Wt1, a11, a21, g1, b1, m1, v1,
        Wt2, a12, a22, g2, b2, m2, v2, Wl, bl,
        (float*)d_out, B);
}